// round 4
// baseline (speedup 1.0000x reference)
#include <cuda_runtime.h>
#include <cstdint>
#include <math.h>

// Problem constants
#define NB   64     // batch
#define NT   256    // time
#define NK   5
#define NX   512
#define NH   512
#define NG   2048   // 4*H
#define NF   1024   // 2*X
#define BT   16384  // NB*NT

// GEMM tile config (mma.sync tf32, 3xTF32 split)
#define BM   128
#define BN   128
#define BK   32
#define SROW 36     // smem row stride in floats (32 + 4 pad)

// ---------------- device scratch (static: no allocations allowed) ----------------
__device__ float d_xg[(size_t)BT * NF];            // 67 MB   x_g_t
__device__ float d_pre[(size_t)NT * NB * NG];      // 134 MB  pre-gates, [t][b][g]
__device__ float d_h[2][NB * NH];                  // ping-pong hidden state
__device__ float d_houts[(size_t)NT * NB * NH];    // 33.5 MB all h_t
__device__ float d_scaleArr[NT];
__device__ float d_shiftArr[NT];
__device__ unsigned d_bar_count;
__device__ unsigned d_bar_gen;

// ---------------- f32x2 packed math helpers (sm_100+) ----------------
__device__ __forceinline__ unsigned long long pack2(float lo, float hi) {
    unsigned long long r;
    asm("mov.b64 %0, {%1, %2};" : "=l"(r) : "f"(lo), "f"(hi));
    return r;
}
__device__ __forceinline__ void fma2(unsigned long long &d, unsigned long long a, unsigned long long b) {
    asm("fma.rn.f32x2 %0, %1, %2, %0;" : "+l"(d) : "l"(a), "l"(b));
}
__device__ __forceinline__ float2 unpack2(unsigned long long v) {
    float2 f;
    asm("mov.b64 {%0, %1}, %2;" : "=f"(f.x), "=f"(f.y) : "l"(v));
    return f;
}

// ---------------- tf32 mma helpers ----------------
__device__ __forceinline__ float tf32_hi(float v) {
    float h;
    asm("cvt.rna.tf32.f32 %0, %1;" : "=f"(h) : "f"(v));
    return h;
}
__device__ __forceinline__ void mma_tf32(float* c, const uint32_t* a, uint32_t b0, uint32_t b1) {
    asm volatile(
        "mma.sync.aligned.m16n8k8.row.col.f32.tf32.tf32.f32 "
        "{%0,%1,%2,%3}, {%4,%5,%6,%7}, {%8,%9}, {%0,%1,%2,%3};"
        : "+f"(c[0]), "+f"(c[1]), "+f"(c[2]), "+f"(c[3])
        : "r"(a[0]), "r"(a[1]), "r"(a[2]), "r"(a[3]), "r"(b0), "r"(b1));
}

// ---------------- kernel 1: build x_g_t = concat(x[:,:,0,:], mean(x[:,:,1:,:])) ----------------
__global__ __launch_bounds__(256) void prep_kernel(const float* __restrict__ x) {
    int idx = blockIdx.x * blockDim.x + threadIdx.x;   // one float4 of xg
    int f4 = idx & 255;
    int bt = idx >> 8;
    if (bt >= BT) return;
    int f = f4 * 4;
    const float* xb = x + (size_t)bt * (NK * NX);
    float4 v;
    if (f < NX) {
        v = *(const float4*)(xb + f);
    } else {
        int xr = f - NX;
        float4 a1 = *(const float4*)(xb + 1 * NX + xr);
        float4 a2 = *(const float4*)(xb + 2 * NX + xr);
        float4 a3 = *(const float4*)(xb + 3 * NX + xr);
        float4 a4 = *(const float4*)(xb + 4 * NX + xr);
        v.x = (a1.x + a2.x + a3.x + a4.x) * 0.25f;
        v.y = (a1.y + a2.y + a3.y + a4.y) * 0.25f;
        v.z = (a1.z + a2.z + a3.z + a4.z) * 0.25f;
        v.w = (a1.w + a2.w + a3.w + a4.w) * 0.25f;
    }
    *(float4*)&d_xg[(size_t)bt * NF + f] = v;
}

// ---------------- kernel 2: tensor-core GEMM (mma.sync tf32, 3xTF32) ----------------
// pre[t][b][g] = xg[bt] @ Wih^T + (bih + bhh).  M=16384, N=2048, K=1024.
// CTA 128x128, BK=32, 8 warps in 4x2, warp tile 32x64, frag grid 2x8 of m16n8k8.
__global__ __launch_bounds__(256) void gemm_mma_kernel(const float* __restrict__ Wih,
                                                       const float* __restrict__ bih,
                                                       const float* __restrict__ bhh) {
    extern __shared__ float sm[];
    float* Ah = sm;                  // [128][36]
    float* Al = sm + 128 * SROW;
    float* Bh = sm + 2 * 128 * SROW;
    float* Bl = sm + 3 * 128 * SROW;

    const int tid = threadIdx.x;
    const int wid = tid >> 5;
    const int lid = tid & 31;
    const int g   = lid >> 2;        // 0..7
    const int tig = lid & 3;         // 0..3
    const int warpM = wid >> 1;      // 0..3 -> rows warpM*32
    const int warpN = wid & 1;       // 0..1 -> cols warpN*64
    const int ntile = blockIdx.x;
    const int mtile = blockIdx.y;

    const float* Ag = d_xg + (size_t)mtile * BM * NF;
    const float* Bg = Wih  + (size_t)ntile * BN * NF;

    const int lrow = tid >> 3;       // 0..31... wait: 256 threads -> idx per j below
    const int lc4  = tid & 7;

    float acc[2][8][4];
#pragma unroll
    for (int i = 0; i < 2; i++)
#pragma unroll
        for (int j = 0; j < 8; j++)
#pragma unroll
            for (int q = 0; q < 4; q++) acc[i][j][q] = 0.f;

    for (int k0 = 0; k0 < NF; k0 += BK) {
        // stage global loads (A and B tiles are both 128x32)
        float4 av[4], bv[4];
#pragma unroll
        for (int j = 0; j < 4; j++) {
            int idx = tid + j * 256;
            int row = idx >> 3, c4 = idx & 7;
            av[j] = *(const float4*)(Ag + (size_t)row * NF + k0 + c4 * 4);
            bv[j] = *(const float4*)(Bg + (size_t)row * NF + k0 + c4 * 4);
        }
        __syncthreads();   // previous iteration's compute done
#pragma unroll
        for (int j = 0; j < 4; j++) {
            int idx = tid + j * 256;
            int row = idx >> 3, c4 = idx & 7;
            float4 h4, l4;
            h4.x = tf32_hi(av[j].x); l4.x = av[j].x - h4.x;
            h4.y = tf32_hi(av[j].y); l4.y = av[j].y - h4.y;
            h4.z = tf32_hi(av[j].z); l4.z = av[j].z - h4.z;
            h4.w = tf32_hi(av[j].w); l4.w = av[j].w - h4.w;
            *(float4*)&Ah[row * SROW + c4 * 4] = h4;
            *(float4*)&Al[row * SROW + c4 * 4] = l4;
            h4.x = tf32_hi(bv[j].x); l4.x = bv[j].x - h4.x;
            h4.y = tf32_hi(bv[j].y); l4.y = bv[j].y - h4.y;
            h4.z = tf32_hi(bv[j].z); l4.z = bv[j].z - h4.z;
            h4.w = tf32_hi(bv[j].w); l4.w = bv[j].w - h4.w;
            *(float4*)&Bh[row * SROW + c4 * 4] = h4;
            *(float4*)&Bl[row * SROW + c4 * 4] = l4;
        }
        __syncthreads();

#pragma unroll
        for (int ks = 0; ks < 4; ks++) {
            const int kk = ks * 8;
            // A fragments (hi and lo) for 2 m-frags
            uint32_t ah[2][4], al[2][4];
#pragma unroll
            for (int mf = 0; mf < 2; mf++) {
                int mb = warpM * 32 + mf * 16;
                ah[mf][0] = __float_as_uint(Ah[(mb + g) * SROW + kk + tig]);
                ah[mf][1] = __float_as_uint(Ah[(mb + g + 8) * SROW + kk + tig]);
                ah[mf][2] = __float_as_uint(Ah[(mb + g) * SROW + kk + tig + 4]);
                ah[mf][3] = __float_as_uint(Ah[(mb + g + 8) * SROW + kk + tig + 4]);
                al[mf][0] = __float_as_uint(Al[(mb + g) * SROW + kk + tig]);
                al[mf][1] = __float_as_uint(Al[(mb + g + 8) * SROW + kk + tig]);
                al[mf][2] = __float_as_uint(Al[(mb + g) * SROW + kk + tig + 4]);
                al[mf][3] = __float_as_uint(Al[(mb + g + 8) * SROW + kk + tig + 4]);
            }
#pragma unroll
            for (int nf = 0; nf < 8; nf++) {
                int nb = warpN * 64 + nf * 8;
                uint32_t bh0 = __float_as_uint(Bh[(nb + g) * SROW + kk + tig]);
                uint32_t bh1 = __float_as_uint(Bh[(nb + g) * SROW + kk + tig + 4]);
                uint32_t bl0 = __float_as_uint(Bl[(nb + g) * SROW + kk + tig]);
                uint32_t bl1 = __float_as_uint(Bl[(nb + g) * SROW + kk + tig + 4]);
#pragma unroll
                for (int mf = 0; mf < 2; mf++) {
                    mma_tf32(acc[mf][nf], ah[mf], bh0, bh1);   // hi*hi
                    mma_tf32(acc[mf][nf], ah[mf], bl0, bl1);   // hi*lo
                    mma_tf32(acc[mf][nf], al[mf], bh0, bh1);   // lo*hi
                }
            }
        }
    }

    // epilogue: add bias, scatter to pre[t][b][g]
#pragma unroll
    for (int nf = 0; nf < 8; nf++) {
        int n = ntile * BN + warpN * 64 + nf * 8 + tig * 2;
        float bias0 = bih[n] + bhh[n];
        float bias1 = bih[n + 1] + bhh[n + 1];
#pragma unroll
        for (int mf = 0; mf < 2; mf++) {
            int ml = warpM * 32 + mf * 16 + g;
            int m0 = mtile * BM + ml;
            int m1 = m0 + 8;
            {
                int b = m0 >> 8, t = m0 & 255;
                float2 v = make_float2(acc[mf][nf][0] + bias0, acc[mf][nf][1] + bias1);
                *(float2*)&d_pre[((size_t)t * NB + b) * NG + n] = v;
            }
            {
                int b = m1 >> 8, t = m1 & 255;
                float2 v = make_float2(acc[mf][nf][2] + bias0, acc[mf][nf][3] + bias1);
                *(float2*)&d_pre[((size_t)t * NB + b) * NG + n] = v;
            }
        }
    }
}

// ---------------- persistent scan kernel: 128 CTAs, custom grid barrier ----------------
__device__ __forceinline__ void grid_barrier(unsigned nb) {
    __threadfence();
    __syncthreads();
    if (threadIdx.x == 0) {
        unsigned my = *(volatile unsigned*)&d_bar_gen;
        if (atomicAdd(&d_bar_count, 1u) == nb - 1u) {
            d_bar_count = 0u;
            __threadfence();
            *(volatile unsigned*)&d_bar_gen = my + 1u;
        } else {
            while (*(volatile unsigned*)&d_bar_gen == my) { }
        }
        __threadfence();
    }
    __syncthreads();
}

// CTA (hg,bg): hg in 0..31 -> 16 h-columns, bg in 0..3 -> 16 batches.
__global__ __launch_bounds__(256) void scan_kernel(const float* __restrict__ Whh) {
    extern __shared__ float smref[];
    float* Ws   = smref;                    // 64 * 513
    float* hs   = smref + 64 * 513;         // 512 * 20 (padded)
    float* zbuf = hs + 512 * 20;            // 64 * 17

    const int tid = threadIdx.x;
    const int cid = blockIdx.x;
    const int hg = cid & 31;
    const int bg = cid >> 5;

    for (int idx = tid; idx < 64 * 512; idx += 256) {
        int r = idx >> 9, k = idx & 511;
        int q = r >> 4, cs = r & 15;
        int G = q * NH + hg * 16 + cs;
        Ws[r * 513 + k] = Whh[(size_t)G * NH + k];
    }

    const int colsub = tid & 15;
    const int bsub = tid >> 4;
    const int col = hg * 16 + colsub;
    const int bb = bg * 16 + bsub;
    d_h[0][bb * NH + col] = 0.f;
    float c = 0.f;

    const int r = tid & 63;
    const int bq = tid >> 6;
    const float* wrow = Ws + r * 513;
    const int q = r >> 4, cs2 = r & 15;
    const int G = q * NH + hg * 16 + cs2;
    const float* hp = hs + bq * 4;

    grid_barrier(gridDim.x);

    for (int t = 0; t < NT; t++) {
        const float* hb = d_h[t & 1];
        for (int idx = tid; idx < 16 * 512; idx += 256) {
            int sb = idx >> 9, k = idx & 511;
            hs[k * 20 + sb] = hb[(bg * 16 + sb) * NH + k];
        }
        __syncthreads();

        unsigned long long acc01 = 0ull, acc23 = 0ull;
#pragma unroll 4
        for (int k = 0; k < 512; k++) {
            float w = wrow[k];
            ulonglong2 hh = *(const ulonglong2*)(hp + k * 20);
            unsigned long long w2 = pack2(w, w);
            fma2(acc01, w2, hh.x);
            fma2(acc23, w2, hh.y);
        }
        const float* prow = d_pre + ((size_t)t * NB + bg * 16 + bq * 4) * NG + G;
        float2 z01 = unpack2(acc01);
        float2 z23 = unpack2(acc23);
        zbuf[r * 17 + bq * 4 + 0] = z01.x + prow[0 * NG];
        zbuf[r * 17 + bq * 4 + 1] = z01.y + prow[1 * NG];
        zbuf[r * 17 + bq * 4 + 2] = z23.x + prow[2 * NG];
        zbuf[r * 17 + bq * 4 + 3] = z23.y + prow[3 * NG];
        __syncthreads();

        float zi = zbuf[(0 * 16 + colsub) * 17 + bsub];
        float zf = zbuf[(1 * 16 + colsub) * 17 + bsub];
        float zg = zbuf[(2 * 16 + colsub) * 17 + bsub];
        float zo = zbuf[(3 * 16 + colsub) * 17 + bsub];
        float ig = 1.f / (1.f + expf(-zi));
        float fg = 1.f / (1.f + expf(-zf));
        float gg = tanhf(zg);
        float og = 1.f / (1.f + expf(-zo));
        c = fg * c + ig * gg;
        float hv = og * tanhf(c);
        d_h[(t + 1) & 1][bb * NH + col] = hv;
        d_houts[(size_t)t * (NB * NH) + bb * NH + col] = hv;

        grid_barrier(gridDim.x);
    }
}

// ---------------- kernel 4: per-t BN stats -> scale/shift ----------------
__global__ __launch_bounds__(256) void stats_kernel(const float* __restrict__ gamma,
                                                    const float* __restrict__ beta) {
    int t = blockIdx.x;
    const float4* p = (const float4*)(d_houts + (size_t)t * (NB * NH));
    float s = 0.f, ss = 0.f;
    for (int i = threadIdx.x; i < (NB * NH) / 4; i += 256) {
        float4 v = p[i];
        s  += v.x + v.y + v.z + v.w;
        ss += v.x * v.x + v.y * v.y + v.z * v.z + v.w * v.w;
    }
#pragma unroll
    for (int o = 16; o > 0; o >>= 1) {
        s  += __shfl_down_sync(0xffffffffu, s, o);
        ss += __shfl_down_sync(0xffffffffu, ss, o);
    }
    __shared__ float rs[8], rss[8];
    int w = threadIdx.x >> 5;
    if ((threadIdx.x & 31) == 0) { rs[w] = s; rss[w] = ss; }
    __syncthreads();
    if (threadIdx.x == 0) {
        float S = 0.f, SS = 0.f;
#pragma unroll
        for (int i = 0; i < 8; i++) { S += rs[i]; SS += rss[i]; }
        float mean = S * (1.f / (NB * NH));
        float var = SS * (1.f / (NB * NH)) - mean * mean;
        float sc = gamma[t] * rsqrtf(var + 1e-5f);
        d_scaleArr[t] = sc;
        d_shiftArr[t] = beta[t] - mean * sc;
    }
}

// ---------------- kernel 5: elu(BN(h)) mean over t -> out[b][h] ----------------
__global__ __launch_bounds__(256) void final_kernel(float* __restrict__ out) {
    int idx = blockIdx.x * 256 + threadIdx.x;
    float acc = 0.f;
#pragma unroll 4
    for (int t = 0; t < NT; t++) {
        float v = d_houts[(size_t)t * (NB * NH) + idx];
        float u = v * d_scaleArr[t] + d_shiftArr[t];
        acc += (u > 0.f) ? u : expm1f(u);
    }
    out[idx] = acc * (1.f / NT);
}

// ---------------- launch ----------------
extern "C" void kernel_launch(void* const* d_in, const int* in_sizes, int n_in,
                              void* d_out, int out_size) {
    const float* x     = (const float*)d_in[0];
    const float* Wih   = (const float*)d_in[1];
    const float* Whh   = (const float*)d_in[2];
    const float* bih   = (const float*)d_in[3];
    const float* bhh   = (const float*)d_in[4];
    const float* gamma = (const float*)d_in[5];
    const float* beta  = (const float*)d_in[6];
    float* out = (float*)d_out;

    prep_kernel<<<BT, 256>>>(x);

    int gsmem = 4 * 128 * SROW * (int)sizeof(float);   // 73,728 B
    cudaFuncSetAttribute(gemm_mma_kernel, cudaFuncAttributeMaxDynamicSharedMemorySize, gsmem);
    dim3 ggrid(NG / BN, BT / BM);   // (16, 128)
    gemm_mma_kernel<<<ggrid, 256, gsmem>>>(Wih, bih, bhh);

    int smem = (64 * 513 + 512 * 20 + 64 * 17) * (int)sizeof(float);   // 176,640 B
    cudaFuncSetAttribute(scan_kernel, cudaFuncAttributeMaxDynamicSharedMemorySize, smem);
    scan_kernel<<<128, 256, smem>>>(Whh);

    stats_kernel<<<NT, 256>>>(gamma, beta);
    final_kernel<<<(NB * NH) / 256, 256>>>(out);
}

// round 5
// speedup vs baseline: 1.1500x; 1.1500x over previous
#include <cuda_runtime.h>
#include <cuda_fp16.h>
#include <cstdint>
#include <math.h>

// Problem constants
#define NB   64     // batch
#define NT   256    // time
#define NK   5
#define NX   512
#define NH   512
#define NG   2048   // 4*H
#define NF   1024   // 2*X
#define BT   16384  // NB*NT

// fp16 GEMM tile config
#define BM   128
#define BN   128
#define BK   32
#define PITCH 40            // smem row pitch in halves (80B) -> ldmatrix conflict-free
#define LOSCALE 2048.0f
#define LOINV   (1.0f/2048.0f)

// ---------------- device scratch (static: no allocations allowed) ----------------
__device__ __half d_xa_h[(size_t)BT * NF];         // 33.5 MB A hi
__device__ __half d_xa_l[(size_t)BT * NF];         // 33.5 MB A lo (x2048)
__device__ __half d_w_h[(size_t)NG * NF];          // 4 MB  W_ih hi
__device__ __half d_w_l[(size_t)NG * NF];          // 4 MB  W_ih lo (x2048)
__device__ float d_pre[(size_t)NT * NB * NG];      // 134 MB  pre-gates, [t][b][g]
__device__ float d_h[2][NB * NH];                  // ping-pong hidden state
__device__ float d_houts[(size_t)NT * NB * NH];    // 33.5 MB all h_t
__device__ float d_scaleArr[NT];
__device__ float d_shiftArr[NT];
__device__ unsigned d_bc[4];                       // per-batch-group barrier count
__device__ unsigned d_bgen[4];                     // per-batch-group barrier generation

// ---------------- f32x2 packed math helpers (sm_100+) ----------------
__device__ __forceinline__ unsigned long long pack2(float lo, float hi) {
    unsigned long long r;
    asm("mov.b64 %0, {%1, %2};" : "=l"(r) : "f"(lo), "f"(hi));
    return r;
}
__device__ __forceinline__ void fma2(unsigned long long &d, unsigned long long a, unsigned long long b) {
    asm("fma.rn.f32x2 %0, %1, %2, %0;" : "+l"(d) : "l"(a), "l"(b));
}
__device__ __forceinline__ float2 unpack2(unsigned long long v) {
    float2 f;
    asm("mov.b64 {%0, %1}, %2;" : "=f"(f.x), "=f"(f.y) : "l"(v));
    return f;
}

// ---------------- mma / ldmatrix helpers (sm_80-era, safe on compute_103) ----------------
__device__ __forceinline__ uint32_t smem_u32(const void* p) {
    uint32_t a;
    asm("{ .reg .u64 t; cvta.to.shared.u64 t, %1; cvt.u32.u64 %0, t; }" : "=r"(a) : "l"(p));
    return a;
}
__device__ __forceinline__ void ldsm4(uint32_t* r, uint32_t addr) {
    asm volatile("ldmatrix.sync.aligned.m8n8.x4.shared.b16 {%0,%1,%2,%3}, [%4];"
                 : "=r"(r[0]), "=r"(r[1]), "=r"(r[2]), "=r"(r[3]) : "r"(addr));
}
__device__ __forceinline__ void mma16(float* c, const uint32_t* a, uint32_t b0, uint32_t b1) {
    asm volatile(
        "mma.sync.aligned.m16n8k16.row.col.f32.f16.f16.f32 "
        "{%0,%1,%2,%3}, {%4,%5,%6,%7}, {%8,%9}, {%0,%1,%2,%3};"
        : "+f"(c[0]), "+f"(c[1]), "+f"(c[2]), "+f"(c[3])
        : "r"(a[0]), "r"(a[1]), "r"(a[2]), "r"(a[3]), "r"(b0), "r"(b1));
}

// ---------------- kernel 1: build x_g_t hi/lo fp16 ----------------
__global__ __launch_bounds__(256) void prep_kernel(const float* __restrict__ x) {
    int idx = blockIdx.x * blockDim.x + threadIdx.x;   // one 4-elem group of xg
    int f4 = idx & 255;
    int bt = idx >> 8;
    if (bt >= BT) return;
    int f = f4 * 4;
    const float* xb = x + (size_t)bt * (NK * NX);
    float4 v;
    if (f < NX) {
        v = *(const float4*)(xb + f);
    } else {
        int xr = f - NX;
        float4 a1 = *(const float4*)(xb + 1 * NX + xr);
        float4 a2 = *(const float4*)(xb + 2 * NX + xr);
        float4 a3 = *(const float4*)(xb + 3 * NX + xr);
        float4 a4 = *(const float4*)(xb + 4 * NX + xr);
        v.x = (a1.x + a2.x + a3.x + a4.x) * 0.25f;
        v.y = (a1.y + a2.y + a3.y + a4.y) * 0.25f;
        v.z = (a1.z + a2.z + a3.z + a4.z) * 0.25f;
        v.w = (a1.w + a2.w + a3.w + a4.w) * 0.25f;
    }
    __half hx = __float2half_rn(v.x), hy = __float2half_rn(v.y);
    __half hz = __float2half_rn(v.z), hw = __float2half_rn(v.w);
    __half lx = __float2half_rn((v.x - __half2float(hx)) * LOSCALE);
    __half ly = __float2half_rn((v.y - __half2float(hy)) * LOSCALE);
    __half lz = __float2half_rn((v.z - __half2float(hz)) * LOSCALE);
    __half lw = __float2half_rn((v.w - __half2float(hw)) * LOSCALE);
    __half2* ph = (__half2*)&d_xa_h[(size_t)bt * NF + f];
    __half2* pl = (__half2*)&d_xa_l[(size_t)bt * NF + f];
    ph[0] = __halves2half2(hx, hy); ph[1] = __halves2half2(hz, hw);
    pl[0] = __halves2half2(lx, ly); pl[1] = __halves2half2(lz, lw);
}

// ---------------- kernel 1b: convert W_ih to hi/lo fp16 ----------------
__global__ __launch_bounds__(256) void wconv_kernel(const float* __restrict__ Wih) {
    int idx = (blockIdx.x * 256 + threadIdx.x) * 4;
    float4 v = *(const float4*)(Wih + idx);
    __half hx = __float2half_rn(v.x), hy = __float2half_rn(v.y);
    __half hz = __float2half_rn(v.z), hw = __float2half_rn(v.w);
    __half lx = __float2half_rn((v.x - __half2float(hx)) * LOSCALE);
    __half ly = __float2half_rn((v.y - __half2float(hy)) * LOSCALE);
    __half lz = __float2half_rn((v.z - __half2float(hz)) * LOSCALE);
    __half lw = __float2half_rn((v.w - __half2float(hw)) * LOSCALE);
    __half2* ph = (__half2*)&d_w_h[idx];
    __half2* pl = (__half2*)&d_w_l[idx];
    ph[0] = __halves2half2(hx, hy); ph[1] = __halves2half2(hz, hw);
    pl[0] = __halves2half2(lx, ly); pl[1] = __halves2half2(lz, lw);
}

// ---------------- kernel 2: fp16x3 tensor-core GEMM ----------------
// pre[t][b][g] = xg @ Wih^T + bias.  M=16384, N=2048, K=1024.
// CTA 128x128, BK=32, 8 warps (4x2), warp tile 32x64, mma m16n8k16, ldmatrix.x4.
// D = accH + accC/2048  (hi*hi  +  (hi*lo' + lo'*hi)/2048)
__global__ __launch_bounds__(256, 1) void gemm16_kernel(const float* __restrict__ bih,
                                                        const float* __restrict__ bhh) {
    extern __shared__ __half hsm[];
    const uint32_t sbase = smem_u32(hsm);
    // matrix offsets in halves: AH=0, AL, BH, BL
    const int MAT = BM * PITCH;   // 5120 halves = 10240 B per matrix

    const int tid = threadIdx.x;
    const int wid = tid >> 5;
    const int lid = tid & 31;
    const int g   = lid >> 2;
    const int tig = lid & 3;
    const int warpM = wid >> 1;      // 0..3
    const int warpN = wid & 1;       // 0..1
    const int ntile = blockIdx.x;
    const int mtile = blockIdx.y;

    float accH[2][8][4], accC[2][8][4];
#pragma unroll
    for (int i = 0; i < 2; i++)
#pragma unroll
        for (int j = 0; j < 8; j++)
#pragma unroll
            for (int q = 0; q < 4; q++) { accH[i][j][q] = 0.f; accC[i][j][q] = 0.f; }

    // staging map: c = tid + j*256 in [0,2048): mat=c>>9, rem=c&511, row=rem>>2, part=rem&3
    for (int k0 = 0; k0 < NF; k0 += BK) {
        uint4 stg[8];
#pragma unroll
        for (int j = 0; j < 8; j++) {
            int c = tid + j * 256;
            int mat = c >> 9, rem = c & 511;
            int row = rem >> 2, part = rem & 3;
            const __half* src;
            if (mat == 0)      src = d_xa_h + (size_t)(mtile * BM + row) * NF;
            else if (mat == 1) src = d_xa_l + (size_t)(mtile * BM + row) * NF;
            else if (mat == 2) src = d_w_h + (size_t)(ntile * BN + row) * NF;
            else               src = d_w_l + (size_t)(ntile * BN + row) * NF;
            stg[j] = *(const uint4*)(src + k0 + part * 8);
        }
        __syncthreads();   // previous compute done
#pragma unroll
        for (int j = 0; j < 8; j++) {
            int c = tid + j * 256;
            int mat = c >> 9, rem = c & 511;
            int row = rem >> 2, part = rem & 3;
            uint32_t addr = sbase + (uint32_t)(mat * MAT + row * PITCH + part * 8) * 2;
            asm volatile("st.shared.v4.b32 [%0], {%1,%2,%3,%4};"
                         :: "r"(addr), "r"(stg[j].x), "r"(stg[j].y), "r"(stg[j].z), "r"(stg[j].w)
                         : "memory");
        }
        __syncthreads();

#pragma unroll
        for (int ks = 0; ks < 2; ks++) {
            // A fragments (hi and scaled-lo) for 2 m-frags
            uint32_t ah[2][4], al[2][4];
            {
                int arow = (lid & 7) + ((lid >> 3) & 1) * 8;
                int akc = ks * 16 + (lid >> 4) * 8;
#pragma unroll
                for (int mf = 0; mf < 2; mf++) {
                    int row = warpM * 32 + mf * 16 + arow;
                    uint32_t a0 = sbase + (uint32_t)(row * PITCH + akc) * 2;
                    ldsm4(ah[mf], a0);
                    ldsm4(al[mf], a0 + (uint32_t)MAT * 2);
                }
            }
            // B pairs: p covers nf = 2p, 2p+1
            int brow0 = (lid & 7) + ((lid >> 4) & 1) * 8;
            int bkc = ks * 16 + ((lid >> 3) & 1) * 8;
#pragma unroll
            for (int p = 0; p < 4; p++) {
                int row = warpN * 64 + p * 16 + brow0;
                uint32_t b0 = sbase + (uint32_t)(2 * MAT + row * PITCH + bkc) * 2;
                uint32_t bh[4], bl[4];
                ldsm4(bh, b0);
                ldsm4(bl, b0 + (uint32_t)MAT * 2);
#pragma unroll
                for (int mf = 0; mf < 2; mf++) {
                    mma16(accH[mf][2 * p],     ah[mf], bh[0], bh[1]);
                    mma16(accC[mf][2 * p],     ah[mf], bl[0], bl[1]);
                    mma16(accC[mf][2 * p],     al[mf], bh[0], bh[1]);
                    mma16(accH[mf][2 * p + 1], ah[mf], bh[2], bh[3]);
                    mma16(accC[mf][2 * p + 1], ah[mf], bl[2], bl[3]);
                    mma16(accC[mf][2 * p + 1], al[mf], bh[2], bh[3]);
                }
            }
        }
    }

    // epilogue: combine, add bias, scatter to pre[t][b][g]
#pragma unroll
    for (int nf = 0; nf < 8; nf++) {
        int n = ntile * BN + warpN * 64 + nf * 8 + tig * 2;
        float bias0 = bih[n] + bhh[n];
        float bias1 = bih[n + 1] + bhh[n + 1];
#pragma unroll
        for (int mf = 0; mf < 2; mf++) {
            int m0 = mtile * BM + warpM * 32 + mf * 16 + g;
            int m1 = m0 + 8;
            {
                int b = m0 >> 8, t = m0 & 255;
                float2 v = make_float2(accH[mf][nf][0] + accC[mf][nf][0] * LOINV + bias0,
                                       accH[mf][nf][1] + accC[mf][nf][1] * LOINV + bias1);
                *(float2*)&d_pre[((size_t)t * NB + b) * NG + n] = v;
            }
            {
                int b = m1 >> 8, t = m1 & 255;
                float2 v = make_float2(accH[mf][nf][2] + accC[mf][nf][2] * LOINV + bias0,
                                       accH[mf][nf][3] + accC[mf][nf][3] * LOINV + bias1);
                *(float2*)&d_pre[((size_t)t * NB + b) * NG + n] = v;
            }
        }
    }
}

// ---------------- persistent scan kernel: 128 CTAs, per-batch-group barriers ----------------
__device__ __forceinline__ void group_barrier(int slot) {
    __threadfence();
    __syncthreads();
    if (threadIdx.x == 0) {
        unsigned my = *(volatile unsigned*)&d_bgen[slot];
        if (atomicAdd(&d_bc[slot], 1u) == 31u) {
            d_bc[slot] = 0u;
            __threadfence();
            *(volatile unsigned*)&d_bgen[slot] = my + 1u;
        } else {
            while (*(volatile unsigned*)&d_bgen[slot] == my) { }
        }
        __threadfence();
    }
    __syncthreads();
}

// CTA (hg,bg): hg in 0..31 -> 16 h-columns, bg in 0..3 -> 16 batches.
__global__ __launch_bounds__(256) void scan_kernel(const float* __restrict__ Whh) {
    extern __shared__ float smref[];
    float* Ws   = smref;                    // 64 * 513
    float* hs   = smref + 64 * 513;         // 512 * 20 (padded)
    float* zbuf = hs + 512 * 20;            // 64 * 17

    const int tid = threadIdx.x;
    const int cid = blockIdx.x;
    const int hg = cid & 31;
    const int bg = cid >> 5;

    for (int idx = tid; idx < 64 * 512; idx += 256) {
        int r = idx >> 9, k = idx & 511;
        int q = r >> 4, cs = r & 15;
        int G = q * NH + hg * 16 + cs;
        Ws[r * 513 + k] = Whh[(size_t)G * NH + k];
    }

    const int colsub = tid & 15;
    const int bsub = tid >> 4;
    const int col = hg * 16 + colsub;
    const int bb = bg * 16 + bsub;
    d_h[0][bb * NH + col] = 0.f;
    float c = 0.f;

    const int r = tid & 63;
    const int bq = tid >> 6;
    const float* wrow = Ws + r * 513;
    const int q = r >> 4, cs2 = r & 15;
    const int G = q * NH + hg * 16 + cs2;
    const float* hp = hs + bq * 4;

    group_barrier(bg);   // h zeros visible within group; Ws loaded via internal syncthreads

    for (int t = 0; t < NT; t++) {
        // prefetch this step's pre-gate values early (hide DRAM latency behind matvec)
        const float* prow = d_pre + ((size_t)t * NB + bg * 16 + bq * 4) * NG + G;
        float pv0 = prow[0 * NG];
        float pv1 = prow[1 * NG];
        float pv2 = prow[2 * NG];
        float pv3 = prow[3 * NG];

        const float* hb = d_h[t & 1];
        for (int idx = tid; idx < 16 * 512; idx += 256) {
            int sb = idx >> 9, k = idx & 511;
            hs[k * 20 + sb] = hb[(bg * 16 + sb) * NH + k];
        }
        __syncthreads();

        unsigned long long acc01 = 0ull, acc23 = 0ull;
#pragma unroll 4
        for (int k = 0; k < 512; k++) {
            float w = wrow[k];
            ulonglong2 hh = *(const ulonglong2*)(hp + k * 20);
            unsigned long long w2 = pack2(w, w);
            fma2(acc01, w2, hh.x);
            fma2(acc23, w2, hh.y);
        }
        float2 z01 = unpack2(acc01);
        float2 z23 = unpack2(acc23);
        zbuf[r * 17 + bq * 4 + 0] = z01.x + pv0;
        zbuf[r * 17 + bq * 4 + 1] = z01.y + pv1;
        zbuf[r * 17 + bq * 4 + 2] = z23.x + pv2;
        zbuf[r * 17 + bq * 4 + 3] = z23.y + pv3;
        __syncthreads();

        float zi = zbuf[(0 * 16 + colsub) * 17 + bsub];
        float zf = zbuf[(1 * 16 + colsub) * 17 + bsub];
        float zg = zbuf[(2 * 16 + colsub) * 17 + bsub];
        float zo = zbuf[(3 * 16 + colsub) * 17 + bsub];
        float ig = 1.f / (1.f + expf(-zi));
        float fg = 1.f / (1.f + expf(-zf));
        float gg = tanhf(zg);
        float og = 1.f / (1.f + expf(-zo));
        c = fg * c + ig * gg;
        float hv = og * tanhf(c);
        d_h[(t + 1) & 1][bb * NH + col] = hv;
        d_houts[(size_t)t * (NB * NH) + bb * NH + col] = hv;

        group_barrier(bg);
    }
}

// ---------------- kernel 4: per-t BN stats -> scale/shift ----------------
__global__ __launch_bounds__(256) void stats_kernel(const float* __restrict__ gamma,
                                                    const float* __restrict__ beta) {
    int t = blockIdx.x;
    const float4* p = (const float4*)(d_houts + (size_t)t * (NB * NH));
    float s = 0.f, ss = 0.f;
    for (int i = threadIdx.x; i < (NB * NH) / 4; i += 256) {
        float4 v = p[i];
        s  += v.x + v.y + v.z + v.w;
        ss += v.x * v.x + v.y * v.y + v.z * v.z + v.w * v.w;
    }
#pragma unroll
    for (int o = 16; o > 0; o >>= 1) {
        s  += __shfl_down_sync(0xffffffffu, s, o);
        ss += __shfl_down_sync(0xffffffffu, ss, o);
    }
    __shared__ float rs[8], rss[8];
    int w = threadIdx.x >> 5;
    if ((threadIdx.x & 31) == 0) { rs[w] = s; rss[w] = ss; }
    __syncthreads();
    if (threadIdx.x == 0) {
        float S = 0.f, SS = 0.f;
#pragma unroll
        for (int i = 0; i < 8; i++) { S += rs[i]; SS += rss[i]; }
        float mean = S * (1.f / (NB * NH));
        float var = SS * (1.f / (NB * NH)) - mean * mean;
        float sc = gamma[t] * rsqrtf(var + 1e-5f);
        d_scaleArr[t] = sc;
        d_shiftArr[t] = beta[t] - mean * sc;
    }
}

// ---------------- kernel 5: elu(BN(h)) mean over t -> out[b][h] ----------------
__global__ __launch_bounds__(256) void final_kernel(float* __restrict__ out) {
    int idx = blockIdx.x * 256 + threadIdx.x;
    float acc = 0.f;
#pragma unroll 4
    for (int t = 0; t < NT; t++) {
        float v = d_houts[(size_t)t * (NB * NH) + idx];
        float u = v * d_scaleArr[t] + d_shiftArr[t];
        acc += (u > 0.f) ? u : expm1f(u);
    }
    out[idx] = acc * (1.f / NT);
}

// ---------------- launch ----------------
extern "C" void kernel_launch(void* const* d_in, const int* in_sizes, int n_in,
                              void* d_out, int out_size) {
    const float* x     = (const float*)d_in[0];
    const float* Wih   = (const float*)d_in[1];
    const float* Whh   = (const float*)d_in[2];
    const float* bih   = (const float*)d_in[3];
    const float* bhh   = (const float*)d_in[4];
    const float* gamma = (const float*)d_in[5];
    const float* beta  = (const float*)d_in[6];
    float* out = (float*)d_out;

    prep_kernel<<<BT, 256>>>(x);
    wconv_kernel<<<(NG * NF / 4) / 256, 256>>>(Wih);

    int gsmem = 4 * BM * PITCH * 2;   // 40960 B
    cudaFuncSetAttribute(gemm16_kernel, cudaFuncAttributeMaxDynamicSharedMemorySize, gsmem);
    dim3 ggrid(NG / BN, BT / BM);     // (16, 128)
    gemm16_kernel<<<ggrid, 256, gsmem>>>(bih, bhh);

    int smem = (64 * 513 + 512 * 20 + 64 * 17) * (int)sizeof(float);   // 176,640 B
    cudaFuncSetAttribute(scan_kernel, cudaFuncAttributeMaxDynamicSharedMemorySize, smem);
    scan_kernel<<<128, 256, smem>>>(Whh);

    stats_kernel<<<NT, 256>>>(gamma, beta);
    final_kernel<<<(NB * NH) / 256, 256>>>(out);
}

// round 6
// speedup vs baseline: 1.5537x; 1.3511x over previous
#include <cuda_runtime.h>
#include <cuda_fp16.h>
#include <cstdint>
#include <math.h>

// Problem constants
#define NB   64     // batch
#define NT   256    // time
#define NK   5
#define NX   512
#define NH   512
#define NG   2048   // 4*H
#define NF   1024   // 2*X
#define BT   16384  // NB*NT

// fp16 GEMM tile config
#define BM   128
#define BN   128
#define BK   32
#define PITCH 40            // smem row pitch in halves (80B) -> ldmatrix conflict-free
#define LOSCALE 2048.0f
#define LOINV   (1.0f/2048.0f)

// ---------------- device scratch (static: no allocations allowed) ----------------
__device__ __half d_xa_h[(size_t)BT * NF];         // 33.5 MB A hi
__device__ __half d_xa_l[(size_t)BT * NF];         // 33.5 MB A lo (x2048)
__device__ __half d_w_h[(size_t)NG * NF];          // 4 MB  W_ih hi
__device__ __half d_w_l[(size_t)NG * NF];          // 4 MB  W_ih lo (x2048)
__device__ float d_pre[(size_t)NT * NB * NG];      // 134 MB  pre-gates, [t][b][g]
__device__ float d_h[2][NB * NH];                  // ping-pong hidden state
__device__ float d_houts[(size_t)NT * NB * NH];    // 33.5 MB all h_t
__device__ float d_scaleArr[NT];
__device__ float d_shiftArr[NT];
__device__ unsigned d_bc[4 * 32];                  // per-group barrier count (128B apart)
__device__ unsigned d_bgen[4 * 32];                // per-group barrier generation (128B apart)

// ---------------- f32x2 packed math helpers (sm_100+) ----------------
__device__ __forceinline__ unsigned long long pack2(float lo, float hi) {
    unsigned long long r;
    asm("mov.b64 %0, {%1, %2};" : "=l"(r) : "f"(lo), "f"(hi));
    return r;
}
__device__ __forceinline__ void fma2(unsigned long long &d, unsigned long long a, unsigned long long b) {
    asm("fma.rn.f32x2 %0, %1, %2, %0;" : "+l"(d) : "l"(a), "l"(b));
}
__device__ __forceinline__ float2 unpack2(unsigned long long v) {
    float2 f;
    asm("mov.b64 {%0, %1}, %2;" : "=f"(f.x), "=f"(f.y) : "l"(v));
    return f;
}

// ---------------- mma / ldmatrix helpers ----------------
__device__ __forceinline__ uint32_t smem_u32(const void* p) {
    uint32_t a;
    asm("{ .reg .u64 t; cvta.to.shared.u64 t, %1; cvt.u32.u64 %0, t; }" : "=r"(a) : "l"(p));
    return a;
}
__device__ __forceinline__ void ldsm4(uint32_t* r, uint32_t addr) {
    asm volatile("ldmatrix.sync.aligned.m8n8.x4.shared.b16 {%0,%1,%2,%3}, [%4];"
                 : "=r"(r[0]), "=r"(r[1]), "=r"(r[2]), "=r"(r[3]) : "r"(addr));
}
__device__ __forceinline__ void mma16(float* c, const uint32_t* a, uint32_t b0, uint32_t b1) {
    asm volatile(
        "mma.sync.aligned.m16n8k16.row.col.f32.f16.f16.f32 "
        "{%0,%1,%2,%3}, {%4,%5,%6,%7}, {%8,%9}, {%0,%1,%2,%3};"
        : "+f"(c[0]), "+f"(c[1]), "+f"(c[2]), "+f"(c[3])
        : "r"(a[0]), "r"(a[1]), "r"(a[2]), "r"(a[3]), "r"(b0), "r"(b1));
}
__device__ __forceinline__ void cp16(uint32_t dst, const void* src) {
    asm volatile("cp.async.cg.shared.global [%0], [%1], 16;" :: "r"(dst), "l"(src) : "memory");
}

// ---------------- kernel 1: build x_g_t hi/lo fp16 ----------------
__global__ __launch_bounds__(256) void prep_kernel(const float* __restrict__ x) {
    int idx = blockIdx.x * blockDim.x + threadIdx.x;
    int f4 = idx & 255;
    int bt = idx >> 8;
    if (bt >= BT) return;
    int f = f4 * 4;
    const float* xb = x + (size_t)bt * (NK * NX);
    float4 v;
    if (f < NX) {
        v = *(const float4*)(xb + f);
    } else {
        int xr = f - NX;
        float4 a1 = *(const float4*)(xb + 1 * NX + xr);
        float4 a2 = *(const float4*)(xb + 2 * NX + xr);
        float4 a3 = *(const float4*)(xb + 3 * NX + xr);
        float4 a4 = *(const float4*)(xb + 4 * NX + xr);
        v.x = (a1.x + a2.x + a3.x + a4.x) * 0.25f;
        v.y = (a1.y + a2.y + a3.y + a4.y) * 0.25f;
        v.z = (a1.z + a2.z + a3.z + a4.z) * 0.25f;
        v.w = (a1.w + a2.w + a3.w + a4.w) * 0.25f;
    }
    __half hx = __float2half_rn(v.x), hy = __float2half_rn(v.y);
    __half hz = __float2half_rn(v.z), hw = __float2half_rn(v.w);
    __half lx = __float2half_rn((v.x - __half2float(hx)) * LOSCALE);
    __half ly = __float2half_rn((v.y - __half2float(hy)) * LOSCALE);
    __half lz = __float2half_rn((v.z - __half2float(hz)) * LOSCALE);
    __half lw = __float2half_rn((v.w - __half2float(hw)) * LOSCALE);
    __half2* ph = (__half2*)&d_xa_h[(size_t)bt * NF + f];
    __half2* pl = (__half2*)&d_xa_l[(size_t)bt * NF + f];
    ph[0] = __halves2half2(hx, hy); ph[1] = __halves2half2(hz, hw);
    pl[0] = __halves2half2(lx, ly); pl[1] = __halves2half2(lz, lw);
}

// ---------------- kernel 1b: convert W_ih to hi/lo fp16 ----------------
__global__ __launch_bounds__(256) void wconv_kernel(const float* __restrict__ Wih) {
    int idx = (blockIdx.x * 256 + threadIdx.x) * 4;
    float4 v = *(const float4*)(Wih + idx);
    __half hx = __float2half_rn(v.x), hy = __float2half_rn(v.y);
    __half hz = __float2half_rn(v.z), hw = __float2half_rn(v.w);
    __half lx = __float2half_rn((v.x - __half2float(hx)) * LOSCALE);
    __half ly = __float2half_rn((v.y - __half2float(hy)) * LOSCALE);
    __half lz = __float2half_rn((v.z - __half2float(hz)) * LOSCALE);
    __half lw = __float2half_rn((v.w - __half2float(hw)) * LOSCALE);
    __half2* ph = (__half2*)&d_w_h[idx];
    __half2* pl = (__half2*)&d_w_l[idx];
    ph[0] = __halves2half2(hx, hy); ph[1] = __halves2half2(hz, hw);
    pl[0] = __halves2half2(lx, ly); pl[1] = __halves2half2(lz, lw);
}

// ---------------- kernel 2: fp16x3 tensor-core GEMM, cp.async double-buffered ----------------
// pre[t][b][g] = xg @ Wih^T + bias.  M=16384, N=2048, K=1024.
__global__ __launch_bounds__(256, 1) void gemm16_kernel(const float* __restrict__ bih,
                                                        const float* __restrict__ bhh) {
    extern __shared__ __half hsm[];
    const uint32_t sbase = smem_u32(hsm);
    const int MAT  = BM * PITCH;     // 5120 halves per matrix
    const int BUFH = 4 * MAT;        // halves per buffer (40,960 B)

    const int tid = threadIdx.x;
    const int wid = tid >> 5;
    const int lid = tid & 31;
    const int g   = lid >> 2;
    const int tig = lid & 3;
    const int warpM = wid >> 1;
    const int warpN = wid & 1;
    const int ntile = blockIdx.x;
    const int mtile = blockIdx.y;

    float accH[2][8][4], accC[2][8][4];
#pragma unroll
    for (int i = 0; i < 2; i++)
#pragma unroll
        for (int j = 0; j < 8; j++)
#pragma unroll
            for (int q = 0; q < 4; q++) { accH[i][j][q] = 0.f; accC[i][j][q] = 0.f; }

    // prefetch: 2048 16-B segments, 8 per thread
    auto prefetch = [&](int i) {
        const int k0 = i * BK;
        const uint32_t sb = sbase + (uint32_t)((i & 1) * BUFH) * 2;
#pragma unroll
        for (int j = 0; j < 8; j++) {
            int c = tid + j * 256;
            int mat = c >> 9, rem = c & 511;
            int row = rem >> 2, part = rem & 3;
            const __half* src;
            if (mat == 0)      src = d_xa_h + (size_t)(mtile * BM + row) * NF;
            else if (mat == 1) src = d_xa_l + (size_t)(mtile * BM + row) * NF;
            else if (mat == 2) src = d_w_h + (size_t)(ntile * BN + row) * NF;
            else               src = d_w_l + (size_t)(ntile * BN + row) * NF;
            uint32_t dst = sb + (uint32_t)(mat * MAT + row * PITCH + part * 8) * 2;
            cp16(dst, src + k0 + part * 8);
        }
        asm volatile("cp.async.commit_group;" ::: "memory");
    };

    prefetch(0);
    for (int i = 0; i < NF / BK; i++) {
        if (i < NF / BK - 1) {
            prefetch(i + 1);
            asm volatile("cp.async.wait_group 1;" ::: "memory");
        } else {
            asm volatile("cp.async.wait_group 0;" ::: "memory");
        }
        __syncthreads();

        const uint32_t boff = sbase + (uint32_t)((i & 1) * BUFH) * 2;
#pragma unroll
        for (int ks = 0; ks < 2; ks++) {
            uint32_t ah[2][4], al[2][4];
            {
                int arow = (lid & 7) + ((lid >> 3) & 1) * 8;
                int akc = ks * 16 + (lid >> 4) * 8;
#pragma unroll
                for (int mf = 0; mf < 2; mf++) {
                    int row = warpM * 32 + mf * 16 + arow;
                    uint32_t a0 = boff + (uint32_t)(row * PITCH + akc) * 2;
                    ldsm4(ah[mf], a0);
                    ldsm4(al[mf], a0 + (uint32_t)MAT * 2);
                }
            }
            int brow0 = (lid & 7) + ((lid >> 4) & 1) * 8;
            int bkc = ks * 16 + ((lid >> 3) & 1) * 8;
#pragma unroll
            for (int p = 0; p < 4; p++) {
                int row = warpN * 64 + p * 16 + brow0;
                uint32_t b0 = boff + (uint32_t)(2 * MAT + row * PITCH + bkc) * 2;
                uint32_t bh[4], bl[4];
                ldsm4(bh, b0);
                ldsm4(bl, b0 + (uint32_t)MAT * 2);
#pragma unroll
                for (int mf = 0; mf < 2; mf++) {
                    mma16(accH[mf][2 * p],     ah[mf], bh[0], bh[1]);
                    mma16(accC[mf][2 * p],     ah[mf], bl[0], bl[1]);
                    mma16(accC[mf][2 * p],     al[mf], bh[0], bh[1]);
                    mma16(accH[mf][2 * p + 1], ah[mf], bh[2], bh[3]);
                    mma16(accC[mf][2 * p + 1], ah[mf], bl[2], bl[3]);
                    mma16(accC[mf][2 * p + 1], al[mf], bh[2], bh[3]);
                }
            }
        }
        __syncthreads();
    }

    // epilogue: combine, add bias, scatter to pre[t][b][g]
#pragma unroll
    for (int nf = 0; nf < 8; nf++) {
        int n = ntile * BN + warpN * 64 + nf * 8 + tig * 2;
        float bias0 = bih[n] + bhh[n];
        float bias1 = bih[n + 1] + bhh[n + 1];
#pragma unroll
        for (int mf = 0; mf < 2; mf++) {
            int m0 = mtile * BM + warpM * 32 + mf * 16 + g;
            int m1 = m0 + 8;
            {
                int b = m0 >> 8, t = m0 & 255;
                float2 v = make_float2(accH[mf][nf][0] + accC[mf][nf][0] * LOINV + bias0,
                                       accH[mf][nf][1] + accC[mf][nf][1] * LOINV + bias1);
                *(float2*)&d_pre[((size_t)t * NB + b) * NG + n] = v;
            }
            {
                int b = m1 >> 8, t = m1 & 255;
                float2 v = make_float2(accH[mf][nf][2] + accC[mf][nf][2] * LOINV + bias0,
                                       accH[mf][nf][3] + accC[mf][nf][3] * LOINV + bias1);
                *(float2*)&d_pre[((size_t)t * NB + b) * NG + n] = v;
            }
        }
    }
}

// ---------------- persistent scan: 128 CTAs, scoped-atomic group barriers ----------------
// arrival: atom.acq_rel.gpu; publish: st.release.gpu; poll: ld.acquire.gpu. No MEMBAR.GPU.
__device__ __forceinline__ void group_bar(int slot, unsigned expected) {
    __syncthreads();
    if (threadIdx.x == 0) {
        unsigned old;
        asm volatile("atom.acq_rel.gpu.global.add.u32 %0, [%1], 1;"
                     : "=r"(old) : "l"(&d_bc[slot * 32]) : "memory");
        if (old == 31u) {
            asm volatile("st.relaxed.gpu.global.u32 [%0], 0;" :: "l"(&d_bc[slot * 32]) : "memory");
            asm volatile("st.release.gpu.global.u32 [%0], %1;"
                         :: "l"(&d_bgen[slot * 32]), "r"(expected) : "memory");
        } else {
            unsigned gv;
            do {
                asm volatile("ld.acquire.gpu.global.u32 %0, [%1];"
                             : "=r"(gv) : "l"(&d_bgen[slot * 32]) : "memory");
            } while (gv != expected);
        }
    }
    __syncthreads();
}

// CTA (hg,bg): hg in 0..31 -> 16 h-columns, bg in 0..3 -> 16 batches.
__global__ __launch_bounds__(256) void scan_kernel(const float* __restrict__ Whh) {
    extern __shared__ float smref[];
    float* Ws   = smref;                    // 64 * 513
    float* hs   = smref + 64 * 513;         // 512 * 20 (padded)
    float* zbuf = hs + 512 * 20;            // 64 * 17

    const int tid = threadIdx.x;
    const int cid = blockIdx.x;
    const int hg = cid & 31;
    const int bg = cid >> 5;

    // barrier generation base (persists across graph replays; monotonically increases)
    unsigned gen = 0;
    if (tid == 0) {
        asm volatile("ld.acquire.gpu.global.u32 %0, [%1];" : "=r"(gen) : "l"(&d_bgen[bg * 32]) : "memory");
    }

    for (int idx = tid; idx < 64 * 512; idx += 256) {
        int r = idx >> 9, k = idx & 511;
        int q = r >> 4, cs = r & 15;
        int G = q * NH + hg * 16 + cs;
        Ws[r * 513 + k] = Whh[(size_t)G * NH + k];
    }

    const int colsub = tid & 15;
    const int bsub = tid >> 4;
    const int col = hg * 16 + colsub;
    const int bb = bg * 16 + bsub;
    d_h[0][bb * NH + col] = 0.f;
    float c = 0.f;

    const int r = tid & 63;
    const int bq = tid >> 6;
    const float* wrow = Ws + r * 513;
    const int q = r >> 4, cs2 = r & 15;
    const int G = q * NH + hg * 16 + cs2;
    const float* hp = hs + bq * 4;

    // staging map: idx = tid + j*256 over 2048 float4s: sb = idx>>7, k4 = idx&127
    const int st_sb = tid >> 7;         // base for j strides below
    group_bar(bg, ++gen);

    for (int t = 0; t < NT; t++) {
        // prefetch this step's pre-gate values early (DRAM latency hidden behind matvec)
        const float* prow = d_pre + ((size_t)t * NB + bg * 16 + bq * 4) * NG + G;
        float pv0 = prow[0 * NG];
        float pv1 = prow[1 * NG];
        float pv2 = prow[2 * NG];
        float pv3 = prow[3 * NG];

        // stage h_{t-1}: 8 independent LDG.128 (MLP=8), then STS
        const float* hb = d_h[t & 1];
        float4 hreg[8];
#pragma unroll
        for (int j = 0; j < 8; j++) {
            int idx = tid + j * 256;
            int sb = idx >> 7, k4 = idx & 127;
            hreg[j] = *(const float4*)(hb + (bg * 16 + sb) * NH + k4 * 4);
        }
#pragma unroll
        for (int j = 0; j < 8; j++) {
            int idx = tid + j * 256;
            int sb = idx >> 7, k4 = idx & 127;
            hs[(k4 * 4 + 0) * 20 + sb] = hreg[j].x;
            hs[(k4 * 4 + 1) * 20 + sb] = hreg[j].y;
            hs[(k4 * 4 + 2) * 20 + sb] = hreg[j].z;
            hs[(k4 * 4 + 3) * 20 + sb] = hreg[j].w;
        }
        __syncthreads();

        unsigned long long acc01 = 0ull, acc23 = 0ull;
#pragma unroll 4
        for (int k = 0; k < 512; k++) {
            float w = wrow[k];
            ulonglong2 hh = *(const ulonglong2*)(hp + k * 20);
            unsigned long long w2 = pack2(w, w);
            fma2(acc01, w2, hh.x);
            fma2(acc23, w2, hh.y);
        }
        float2 z01 = unpack2(acc01);
        float2 z23 = unpack2(acc23);
        zbuf[r * 17 + bq * 4 + 0] = z01.x + pv0;
        zbuf[r * 17 + bq * 4 + 1] = z01.y + pv1;
        zbuf[r * 17 + bq * 4 + 2] = z23.x + pv2;
        zbuf[r * 17 + bq * 4 + 3] = z23.y + pv3;
        __syncthreads();

        float zi = zbuf[(0 * 16 + colsub) * 17 + bsub];
        float zf = zbuf[(1 * 16 + colsub) * 17 + bsub];
        float zg = zbuf[(2 * 16 + colsub) * 17 + bsub];
        float zo = zbuf[(3 * 16 + colsub) * 17 + bsub];
        float ig = 1.f / (1.f + expf(-zi));
        float fg = 1.f / (1.f + expf(-zf));
        float gg = tanhf(zg);
        float og = 1.f / (1.f + expf(-zo));
        c = fg * c + ig * gg;
        float hv = og * tanhf(c);
        d_h[(t + 1) & 1][bb * NH + col] = hv;
        d_houts[(size_t)t * (NB * NH) + bb * NH + col] = hv;

        group_bar(bg, ++gen);
    }
}

// ---------------- kernel 4: per-t BN stats -> scale/shift ----------------
__global__ __launch_bounds__(256) void stats_kernel(const float* __restrict__ gamma,
                                                    const float* __restrict__ beta) {
    int t = blockIdx.x;
    const float4* p = (const float4*)(d_houts + (size_t)t * (NB * NH));
    float s = 0.f, ss = 0.f;
    for (int i = threadIdx.x; i < (NB * NH) / 4; i += 256) {
        float4 v = p[i];
        s  += v.x + v.y + v.z + v.w;
        ss += v.x * v.x + v.y * v.y + v.z * v.z + v.w * v.w;
    }
#pragma unroll
    for (int o = 16; o > 0; o >>= 1) {
        s  += __shfl_down_sync(0xffffffffu, s, o);
        ss += __shfl_down_sync(0xffffffffu, ss, o);
    }
    __shared__ float rs[8], rss[8];
    int w = threadIdx.x >> 5;
    if ((threadIdx.x & 31) == 0) { rs[w] = s; rss[w] = ss; }
    __syncthreads();
    if (threadIdx.x == 0) {
        float S = 0.f, SS = 0.f;
#pragma unroll
        for (int i = 0; i < 8; i++) { S += rs[i]; SS += rss[i]; }
        float mean = S * (1.f / (NB * NH));
        float var = SS * (1.f / (NB * NH)) - mean * mean;
        float sc = gamma[t] * rsqrtf(var + 1e-5f);
        d_scaleArr[t] = sc;
        d_shiftArr[t] = beta[t] - mean * sc;
    }
}

// ---------------- kernel 5: elu(BN(h)) mean over t -> out[b][h] ----------------
__global__ __launch_bounds__(256) void final_kernel(float* __restrict__ out) {
    int idx = blockIdx.x * 256 + threadIdx.x;
    float acc = 0.f;
#pragma unroll 4
    for (int t = 0; t < NT; t++) {
        float v = d_houts[(size_t)t * (NB * NH) + idx];
        float u = v * d_scaleArr[t] + d_shiftArr[t];
        acc += (u > 0.f) ? u : expm1f(u);
    }
    out[idx] = acc * (1.f / NT);
}

// ---------------- launch ----------------
extern "C" void kernel_launch(void* const* d_in, const int* in_sizes, int n_in,
                              void* d_out, int out_size) {
    const float* x     = (const float*)d_in[0];
    const float* Wih   = (const float*)d_in[1];
    const float* Whh   = (const float*)d_in[2];
    const float* bih   = (const float*)d_in[3];
    const float* bhh   = (const float*)d_in[4];
    const float* gamma = (const float*)d_in[5];
    const float* beta  = (const float*)d_in[6];
    float* out = (float*)d_out;

    prep_kernel<<<BT, 256>>>(x);
    wconv_kernel<<<(NG * NF / 4) / 256, 256>>>(Wih);

    int gsmem = 2 * 4 * BM * PITCH * 2;   // 81,920 B (double buffer)
    cudaFuncSetAttribute(gemm16_kernel, cudaFuncAttributeMaxDynamicSharedMemorySize, gsmem);
    dim3 ggrid(NG / BN, BT / BM);         // (16, 128)
    gemm16_kernel<<<ggrid, 256, gsmem>>>(bih, bhh);

    int smem = (64 * 513 + 512 * 20 + 64 * 17) * (int)sizeof(float);   // 176,640 B
    cudaFuncSetAttribute(scan_kernel, cudaFuncAttributeMaxDynamicSharedMemorySize, smem);
    scan_kernel<<<128, 256, smem>>>(Whh);

    stats_kernel<<<NT, 256>>>(gamma, beta);
    final_kernel<<<(NB * NH) / 256, 256>>>(out);
}

// round 7
// speedup vs baseline: 3.2419x; 2.0866x over previous
#include <cuda_runtime.h>
#include <cuda_fp16.h>
#include <cstdint>
#include <math.h>

// Problem constants
#define NB   64     // batch
#define NT   256    // time
#define NK   5
#define NX   512
#define NH   512
#define NG   2048   // 4*H
#define NF   1024   // 2*X
#define BT   16384  // NB*NT

// fp16 GEMM tile config
#define BM   128
#define BN   128
#define BK   32
#define PITCH 40            // smem row pitch in halves (80B) -> ldmatrix conflict-free
#define LOSCALE 2048.0f
#define LOINV   (1.0f/2048.0f)

// scan smem layout (in halves): Ws 64x520 (hi,lo), Hs 16x520 (hi,lo), then zbuf
#define WPITCH 520

// ---------------- device scratch (static: no allocations allowed) ----------------
__device__ __half d_xa_h[(size_t)BT * NF];         // A hi
__device__ __half d_xa_l[(size_t)BT * NF];         // A lo (x2048)
__device__ __half d_w_h[(size_t)NG * NF];          // W_ih hi
__device__ __half d_w_l[(size_t)NG * NF];          // W_ih lo (x2048)
__device__ __half d_whh_h[(size_t)NG * NH];        // W_hh hi
__device__ __half d_whh_l[(size_t)NG * NH];        // W_hh lo (x2048)
__device__ __half d_hh_h[2][NB * NH];              // h ping-pong hi
__device__ __half d_hh_l[2][NB * NH];              // h ping-pong lo
__device__ float d_pre[(size_t)NT * NB * NG];      // pre-gates, [t][b][g]
__device__ float d_houts[(size_t)NT * NB * NH];    // all h_t (fp32, for BN)
__device__ float d_scaleArr[NT];
__device__ float d_shiftArr[NT];
__device__ unsigned d_flag[128 * 32];              // per-CTA generation flags, 128B apart

// ---------------- mma / ldmatrix helpers ----------------
__device__ __forceinline__ uint32_t smem_u32(const void* p) {
    uint32_t a;
    asm("{ .reg .u64 t; cvta.to.shared.u64 t, %1; cvt.u32.u64 %0, t; }" : "=r"(a) : "l"(p));
    return a;
}
__device__ __forceinline__ void ldsm4(uint32_t* r, uint32_t addr) {
    asm volatile("ldmatrix.sync.aligned.m8n8.x4.shared.b16 {%0,%1,%2,%3}, [%4];"
                 : "=r"(r[0]), "=r"(r[1]), "=r"(r[2]), "=r"(r[3]) : "r"(addr));
}
__device__ __forceinline__ void ldsm2(uint32_t* r, uint32_t addr) {
    asm volatile("ldmatrix.sync.aligned.m8n8.x2.shared.b16 {%0,%1}, [%2];"
                 : "=r"(r[0]), "=r"(r[1]) : "r"(addr));
}
__device__ __forceinline__ void mma16(float* c, const uint32_t* a, uint32_t b0, uint32_t b1) {
    asm volatile(
        "mma.sync.aligned.m16n8k16.row.col.f32.f16.f16.f32 "
        "{%0,%1,%2,%3}, {%4,%5,%6,%7}, {%8,%9}, {%0,%1,%2,%3};"
        : "+f"(c[0]), "+f"(c[1]), "+f"(c[2]), "+f"(c[3])
        : "r"(a[0]), "r"(a[1]), "r"(a[2]), "r"(a[3]), "r"(b0), "r"(b1));
}
__device__ __forceinline__ void cp16(uint32_t dst, const void* src) {
    asm volatile("cp.async.cg.shared.global [%0], [%1], 16;" :: "r"(dst), "l"(src) : "memory");
}

// ---------------- kernel 1: build x_g_t hi/lo fp16 ----------------
__global__ __launch_bounds__(256) void prep_kernel(const float* __restrict__ x) {
    int idx = blockIdx.x * blockDim.x + threadIdx.x;
    int f4 = idx & 255;
    int bt = idx >> 8;
    if (bt >= BT) return;
    int f = f4 * 4;
    const float* xb = x + (size_t)bt * (NK * NX);
    float4 v;
    if (f < NX) {
        v = *(const float4*)(xb + f);
    } else {
        int xr = f - NX;
        float4 a1 = *(const float4*)(xb + 1 * NX + xr);
        float4 a2 = *(const float4*)(xb + 2 * NX + xr);
        float4 a3 = *(const float4*)(xb + 3 * NX + xr);
        float4 a4 = *(const float4*)(xb + 4 * NX + xr);
        v.x = (a1.x + a2.x + a3.x + a4.x) * 0.25f;
        v.y = (a1.y + a2.y + a3.y + a4.y) * 0.25f;
        v.z = (a1.z + a2.z + a3.z + a4.z) * 0.25f;
        v.w = (a1.w + a2.w + a3.w + a4.w) * 0.25f;
    }
    __half hx = __float2half_rn(v.x), hy = __float2half_rn(v.y);
    __half hz = __float2half_rn(v.z), hw = __float2half_rn(v.w);
    __half lx = __float2half_rn((v.x - __half2float(hx)) * LOSCALE);
    __half ly = __float2half_rn((v.y - __half2float(hy)) * LOSCALE);
    __half lz = __float2half_rn((v.z - __half2float(hz)) * LOSCALE);
    __half lw = __float2half_rn((v.w - __half2float(hw)) * LOSCALE);
    __half2* ph = (__half2*)&d_xa_h[(size_t)bt * NF + f];
    __half2* pl = (__half2*)&d_xa_l[(size_t)bt * NF + f];
    ph[0] = __halves2half2(hx, hy); ph[1] = __halves2half2(hz, hw);
    pl[0] = __halves2half2(lx, ly); pl[1] = __halves2half2(lz, lw);
}

// ---------------- kernel 1b: convert W_ih to hi/lo fp16 ----------------
__global__ __launch_bounds__(256) void wconv_kernel(const float* __restrict__ Wih) {
    int idx = (blockIdx.x * 256 + threadIdx.x) * 4;
    float4 v = *(const float4*)(Wih + idx);
    __half hx = __float2half_rn(v.x), hy = __float2half_rn(v.y);
    __half hz = __float2half_rn(v.z), hw = __float2half_rn(v.w);
    __half lx = __float2half_rn((v.x - __half2float(hx)) * LOSCALE);
    __half ly = __float2half_rn((v.y - __half2float(hy)) * LOSCALE);
    __half lz = __float2half_rn((v.z - __half2float(hz)) * LOSCALE);
    __half lw = __float2half_rn((v.w - __half2float(hw)) * LOSCALE);
    __half2* ph = (__half2*)&d_w_h[idx];
    __half2* pl = (__half2*)&d_w_l[idx];
    ph[0] = __halves2half2(hx, hy); ph[1] = __halves2half2(hz, hw);
    pl[0] = __halves2half2(lx, ly); pl[1] = __halves2half2(lz, lw);
}

// ---------------- kernel 1c: convert W_hh to hi/lo fp16 ----------------
__global__ __launch_bounds__(256) void whhconv_kernel(const float* __restrict__ Whh) {
    int idx = (blockIdx.x * 256 + threadIdx.x) * 4;   // over NG*NH
    float4 v = *(const float4*)(Whh + idx);
    __half hx = __float2half_rn(v.x), hy = __float2half_rn(v.y);
    __half hz = __float2half_rn(v.z), hw = __float2half_rn(v.w);
    __half lx = __float2half_rn((v.x - __half2float(hx)) * LOSCALE);
    __half ly = __float2half_rn((v.y - __half2float(hy)) * LOSCALE);
    __half lz = __float2half_rn((v.z - __half2float(hz)) * LOSCALE);
    __half lw = __float2half_rn((v.w - __half2float(hw)) * LOSCALE);
    __half2* ph = (__half2*)&d_whh_h[idx];
    __half2* pl = (__half2*)&d_whh_l[idx];
    ph[0] = __halves2half2(hx, hy); ph[1] = __halves2half2(hz, hw);
    pl[0] = __halves2half2(lx, ly); pl[1] = __halves2half2(lz, lw);
}

// ---------------- kernel 2: fp16x3 tensor-core GEMM, cp.async double-buffered ----------------
__global__ __launch_bounds__(256, 1) void gemm16_kernel(const float* __restrict__ bih,
                                                        const float* __restrict__ bhh) {
    extern __shared__ __half hsm[];
    const uint32_t sbase = smem_u32(hsm);
    const int MAT  = BM * PITCH;
    const int BUFH = 4 * MAT;

    const int tid = threadIdx.x;
    const int wid = tid >> 5;
    const int lid = tid & 31;
    const int g   = lid >> 2;
    const int tig = lid & 3;
    const int warpM = wid >> 1;
    const int warpN = wid & 1;
    const int ntile = blockIdx.x;
    const int mtile = blockIdx.y;

    float accH[2][8][4], accC[2][8][4];
#pragma unroll
    for (int i = 0; i < 2; i++)
#pragma unroll
        for (int j = 0; j < 8; j++)
#pragma unroll
            for (int q = 0; q < 4; q++) { accH[i][j][q] = 0.f; accC[i][j][q] = 0.f; }

    auto prefetch = [&](int i) {
        const int k0 = i * BK;
        const uint32_t sb = sbase + (uint32_t)((i & 1) * BUFH) * 2;
#pragma unroll
        for (int j = 0; j < 8; j++) {
            int c = tid + j * 256;
            int mat = c >> 9, rem = c & 511;
            int row = rem >> 2, part = rem & 3;
            const __half* src;
            if (mat == 0)      src = d_xa_h + (size_t)(mtile * BM + row) * NF;
            else if (mat == 1) src = d_xa_l + (size_t)(mtile * BM + row) * NF;
            else if (mat == 2) src = d_w_h + (size_t)(ntile * BN + row) * NF;
            else               src = d_w_l + (size_t)(ntile * BN + row) * NF;
            uint32_t dst = sb + (uint32_t)(mat * MAT + row * PITCH + part * 8) * 2;
            cp16(dst, src + k0 + part * 8);
        }
        asm volatile("cp.async.commit_group;" ::: "memory");
    };

    prefetch(0);
    for (int i = 0; i < NF / BK; i++) {
        if (i < NF / BK - 1) {
            prefetch(i + 1);
            asm volatile("cp.async.wait_group 1;" ::: "memory");
        } else {
            asm volatile("cp.async.wait_group 0;" ::: "memory");
        }
        __syncthreads();

        const uint32_t boff = sbase + (uint32_t)((i & 1) * BUFH) * 2;
#pragma unroll
        for (int ks = 0; ks < 2; ks++) {
            uint32_t ah[2][4], al[2][4];
            {
                int arow = (lid & 7) + ((lid >> 3) & 1) * 8;
                int akc = ks * 16 + (lid >> 4) * 8;
#pragma unroll
                for (int mf = 0; mf < 2; mf++) {
                    int row = warpM * 32 + mf * 16 + arow;
                    uint32_t a0 = boff + (uint32_t)(row * PITCH + akc) * 2;
                    ldsm4(ah[mf], a0);
                    ldsm4(al[mf], a0 + (uint32_t)MAT * 2);
                }
            }
            int brow0 = (lid & 7) + ((lid >> 4) & 1) * 8;
            int bkc = ks * 16 + ((lid >> 3) & 1) * 8;
#pragma unroll
            for (int p = 0; p < 4; p++) {
                int row = warpN * 64 + p * 16 + brow0;
                uint32_t b0 = boff + (uint32_t)(2 * MAT + row * PITCH + bkc) * 2;
                uint32_t bh[4], bl[4];
                ldsm4(bh, b0);
                ldsm4(bl, b0 + (uint32_t)MAT * 2);
#pragma unroll
                for (int mf = 0; mf < 2; mf++) {
                    mma16(accH[mf][2 * p],     ah[mf], bh[0], bh[1]);
                    mma16(accC[mf][2 * p],     ah[mf], bl[0], bl[1]);
                    mma16(accC[mf][2 * p],     al[mf], bh[0], bh[1]);
                    mma16(accH[mf][2 * p + 1], ah[mf], bh[2], bh[3]);
                    mma16(accC[mf][2 * p + 1], ah[mf], bl[2], bl[3]);
                    mma16(accC[mf][2 * p + 1], al[mf], bh[2], bh[3]);
                }
            }
        }
        __syncthreads();
    }

#pragma unroll
    for (int nf = 0; nf < 8; nf++) {
        int n = ntile * BN + warpN * 64 + nf * 8 + tig * 2;
        float bias0 = bih[n] + bhh[n];
        float bias1 = bih[n + 1] + bhh[n + 1];
#pragma unroll
        for (int mf = 0; mf < 2; mf++) {
            int m0 = mtile * BM + warpM * 32 + mf * 16 + g;
            int m1 = m0 + 8;
            {
                int b = m0 >> 8, t = m0 & 255;
                float2 v = make_float2(accH[mf][nf][0] + accC[mf][nf][0] * LOINV + bias0,
                                       accH[mf][nf][1] + accC[mf][nf][1] * LOINV + bias1);
                *(float2*)&d_pre[((size_t)t * NB + b) * NG + n] = v;
            }
            {
                int b = m1 >> 8, t = m1 & 255;
                float2 v = make_float2(accH[mf][nf][2] + accC[mf][nf][2] * LOINV + bias0,
                                       accH[mf][nf][3] + accC[mf][nf][3] * LOINV + bias1);
                *(float2*)&d_pre[((size_t)t * NB + b) * NG + n] = v;
            }
        }
    }
}

// ---------------- kernel 3: tensor-core persistent scan ----------------
// 128 CTAs (hg 0..31 x bg 0..3), 512 threads. Flag-based group barrier, no atomics.
// Per step: z[64 rows][16 batch] = Whh_slice @ h^T via mma m16n8k16 fp16 hi/lo.
__global__ __launch_bounds__(512) void scan_kernel() {
    extern __shared__ char smraw[];
    __half* WsH = (__half*)smraw;                 // 64 x 520
    __half* WsL = WsH + 64 * WPITCH;
    __half* HsH = WsL + 64 * WPITCH;              // 16 x 520
    __half* HsL = HsH + 16 * WPITCH;
    float*  zb  = (float*)(HsL + 16 * WPITCH);    // 2 x 64 x 17
    unsigned* sbase_p = (unsigned*)(zb + 2 * 64 * 17);

    const int tid = threadIdx.x;
    const int cid = blockIdx.x;
    const int hg = cid & 31;
    const int bg = cid >> 5;

    if (tid == 0) {
        unsigned b;
        asm volatile("ld.acquire.gpu.global.u32 %0, [%1];" : "=r"(b) : "l"(&d_flag[cid * 32]) : "memory");
        *sbase_p = b;
    }

    // load W_hh slice hi/lo: rows r=q*16+cs -> gate G = q*512 + hg*16 + cs
    for (int i = tid; i < 4096; i += 512) {
        int r = i >> 6, k8 = (i & 63) * 8;
        int G = (r >> 4) * NH + hg * 16 + (r & 15);
        *(uint4*)&WsH[r * WPITCH + k8] = *(const uint4*)&d_whh_h[(size_t)G * NH + k8];
        *(uint4*)&WsL[r * WPITCH + k8] = *(const uint4*)&d_whh_l[(size_t)G * NH + k8];
    }
    // zero h staging (h_{-1} = 0): 2 x 16 x 520 halves = 2080 uint4
    for (int i = tid; i < 2080; i += 512) {
        ((uint4*)HsH)[i] = make_uint4(0u, 0u, 0u, 0u);
    }
    __syncthreads();
    const unsigned base = *sbase_p;

    // matvec warp mapping: 16 warps = 4(m) x 2(n) x 2(k-half)
    const int lid = tid & 31;
    const int wid = tid >> 5;
    const int kh = wid >> 3;
    const int w8 = wid & 7;
    const int mq = w8 & 3;          // rows mq*16
    const int nq = w8 >> 2;         // batches nq*8
    const uint32_t sb32 = smem_u32(smraw);
    const int arow = mq * 16 + (lid & 7) + ((lid >> 3) & 1) * 8;
    const uint32_t a_base = sb32 + (uint32_t)(arow * WPITCH + (lid >> 4) * 8 + kh * 256) * 2;
    const uint32_t ALO = (uint32_t)(64 * WPITCH) * 2;
    const int brow = nq * 8 + (lid & 7);
    const uint32_t b_base = sb32 + (uint32_t)(128 * WPITCH) * 2
                          + (uint32_t)(brow * WPITCH + ((lid >> 3) & 1) * 8 + kh * 256) * 2;
    const uint32_t BLO = (uint32_t)(16 * WPITCH) * 2;

    // cell mapping (tid < 256)
    const int colsub = tid & 15;
    const int bsub = (tid >> 4) & 15;
    const int col = hg * 16 + colsub;
    const int bb = bg * 16 + bsub;
    float c = 0.f;

    for (int t = 0; t < NT; t++) {
        // prefetch pre-gate values (consumed in gate phase)
        float pv0 = 0.f, pv1 = 0.f, pv2 = 0.f, pv3 = 0.f;
        if (tid < 256) {
            const float* pr = d_pre + ((size_t)t * NB + bb) * NG + col;
            pv0 = pr[0]; pv1 = pr[512]; pv2 = pr[1024]; pv3 = pr[1536];
        }
        if (t > 0) {
            if (tid < 32) {
                unsigned target = base + (unsigned)t;
                const unsigned* fl = &d_flag[(bg * 32 + tid) * 32];
                unsigned v;
                do {
                    asm volatile("ld.acquire.gpu.global.u32 %0, [%1];" : "=r"(v) : "l"(fl) : "memory");
                } while ((int)(v - target) < 0);
            }
            __syncthreads();
            // stage h_{t-1} hi/lo: 1024 uint4 each, 2 per thread per array
            const __half* srcH = d_hh_h[(t + 1) & 1];
            const __half* srcL = d_hh_l[(t + 1) & 1];
#pragma unroll
            for (int j = 0; j < 2; j++) {
                int i = tid + j * 512;
                int sb = i >> 6, k8 = (i & 63) * 8;
                *(uint4*)&HsH[sb * WPITCH + k8] = *(const uint4*)&srcH[(bg * 16 + sb) * NH + k8];
                *(uint4*)&HsL[sb * WPITCH + k8] = *(const uint4*)&srcL[(bg * 16 + sb) * NH + k8];
            }
        }
        __syncthreads();

        // matvec: 16 k-steps of k16 per warp
        float aH[4] = {0, 0, 0, 0}, aC1[4] = {0, 0, 0, 0}, aC2[4] = {0, 0, 0, 0};
        uint32_t aaddr = a_base, baddr = b_base;
#pragma unroll
        for (int kk = 0; kk < 16; kk++) {
            uint32_t ah[4], al[4], bh[2], bl[2];
            ldsm4(ah, aaddr);
            ldsm4(al, aaddr + ALO);
            ldsm2(bh, baddr);
            ldsm2(bl, baddr + BLO);
            mma16(aH,  ah, bh[0], bh[1]);
            mma16(aC1, ah, bl[0], bl[1]);
            mma16(aC2, al, bh[0], bh[1]);
            aaddr += 32; baddr += 32;
        }
        {
            float* z = zb + kh * (64 * 17);
            int zr = mq * 16 + (lid >> 2);
            int zc = nq * 8 + (lid & 3) * 2;
            z[zr * 17 + zc]           = aH[0] + (aC1[0] + aC2[0]) * LOINV;
            z[zr * 17 + zc + 1]       = aH[1] + (aC1[1] + aC2[1]) * LOINV;
            z[(zr + 8) * 17 + zc]     = aH[2] + (aC1[2] + aC2[2]) * LOINV;
            z[(zr + 8) * 17 + zc + 1] = aH[3] + (aC1[3] + aC2[3]) * LOINV;
        }
        __syncthreads();

        if (tid < 256) {
            float zi = zb[(0 * 16 + colsub) * 17 + bsub] + zb[64 * 17 + (0 * 16 + colsub) * 17 + bsub] + pv0;
            float zf = zb[(1 * 16 + colsub) * 17 + bsub] + zb[64 * 17 + (1 * 16 + colsub) * 17 + bsub] + pv1;
            float zg = zb[(2 * 16 + colsub) * 17 + bsub] + zb[64 * 17 + (2 * 16 + colsub) * 17 + bsub] + pv2;
            float zo = zb[(3 * 16 + colsub) * 17 + bsub] + zb[64 * 17 + (3 * 16 + colsub) * 17 + bsub] + pv3;
            float ig = 1.f / (1.f + expf(-zi));
            float fg = 1.f / (1.f + expf(-zf));
            float gg = tanhf(zg);
            float og = 1.f / (1.f + expf(-zo));
            c = fg * c + ig * gg;
            float hv = og * tanhf(c);
            d_houts[(size_t)t * (NB * NH) + bb * NH + col] = hv;
            __half hh = __float2half_rn(hv);
            __half hl = __float2half_rn((hv - __half2float(hh)) * LOSCALE);
            d_hh_h[t & 1][bb * NH + col] = hh;
            d_hh_l[t & 1][bb * NH + col] = hl;
        }
        __syncthreads();
        if (tid == 0) {
            asm volatile("st.release.gpu.global.u32 [%0], %1;"
                         :: "l"(&d_flag[cid * 32]), "r"(base + (unsigned)t + 1u) : "memory");
        }
    }
}

// ---------------- kernel 4: per-t BN stats -> scale/shift ----------------
__global__ __launch_bounds__(256) void stats_kernel(const float* __restrict__ gamma,
                                                    const float* __restrict__ beta) {
    int t = blockIdx.x;
    const float4* p = (const float4*)(d_houts + (size_t)t * (NB * NH));
    float s = 0.f, ss = 0.f;
    for (int i = threadIdx.x; i < (NB * NH) / 4; i += 256) {
        float4 v = p[i];
        s  += v.x + v.y + v.z + v.w;
        ss += v.x * v.x + v.y * v.y + v.z * v.z + v.w * v.w;
    }
#pragma unroll
    for (int o = 16; o > 0; o >>= 1) {
        s  += __shfl_down_sync(0xffffffffu, s, o);
        ss += __shfl_down_sync(0xffffffffu, ss, o);
    }
    __shared__ float rs[8], rss[8];
    int w = threadIdx.x >> 5;
    if ((threadIdx.x & 31) == 0) { rs[w] = s; rss[w] = ss; }
    __syncthreads();
    if (threadIdx.x == 0) {
        float S = 0.f, SS = 0.f;
#pragma unroll
        for (int i = 0; i < 8; i++) { S += rs[i]; SS += rss[i]; }
        float mean = S * (1.f / (NB * NH));
        float var = SS * (1.f / (NB * NH)) - mean * mean;
        float sc = gamma[t] * rsqrtf(var + 1e-5f);
        d_scaleArr[t] = sc;
        d_shiftArr[t] = beta[t] - mean * sc;
    }
}

// ---------------- kernel 5: elu(BN(h)) mean over t -> out[b][h] ----------------
__global__ __launch_bounds__(256) void final_kernel(float* __restrict__ out) {
    int idx = blockIdx.x * 256 + threadIdx.x;
    float acc = 0.f;
#pragma unroll 4
    for (int t = 0; t < NT; t++) {
        float v = d_houts[(size_t)t * (NB * NH) + idx];
        float u = v * d_scaleArr[t] + d_shiftArr[t];
        acc += (u > 0.f) ? u : expm1f(u);
    }
    out[idx] = acc * (1.f / NT);
}

// ---------------- launch ----------------
extern "C" void kernel_launch(void* const* d_in, const int* in_sizes, int n_in,
                              void* d_out, int out_size) {
    const float* x     = (const float*)d_in[0];
    const float* Wih   = (const float*)d_in[1];
    const float* Whh   = (const float*)d_in[2];
    const float* bih   = (const float*)d_in[3];
    const float* bhh   = (const float*)d_in[4];
    const float* gamma = (const float*)d_in[5];
    const float* beta  = (const float*)d_in[6];
    float* out = (float*)d_out;

    prep_kernel<<<BT, 256>>>(x);
    wconv_kernel<<<(NG * NF / 4) / 256, 256>>>(Wih);
    whhconv_kernel<<<(NG * NH / 4) / 256, 256>>>(Whh);

    int gsmem = 2 * 4 * BM * PITCH * 2;   // 81,920 B
    cudaFuncSetAttribute(gemm16_kernel, cudaFuncAttributeMaxDynamicSharedMemorySize, gsmem);
    dim3 ggrid(NG / BN, BT / BM);         // (16, 128)
    gemm16_kernel<<<ggrid, 256, gsmem>>>(bih, bhh);

    // scan smem: (64+16)*520*2 halves *2B + zbuf 2*64*17*4B + 16
    int ssmem = (64 * WPITCH + 64 * WPITCH + 16 * WPITCH + 16 * WPITCH) * 2
              + 2 * 64 * 17 * 4 + 16;     // 175,120 B
    cudaFuncSetAttribute(scan_kernel, cudaFuncAttributeMaxDynamicSharedMemorySize, ssmem);
    scan_kernel<<<128, 512, ssmem>>>();

    stats_kernel<<<NT, 256>>>(gamma, beta);
    final_kernel<<<(NB * NH) / 256, 256>>>(out);
}

// round 8
// speedup vs baseline: 3.4023x; 1.0495x over previous
#include <cuda_runtime.h>
#include <cuda_fp16.h>
#include <cstdint>
#include <math.h>

// Problem constants
#define NB   64     // batch
#define NT   256    // time
#define NK   5
#define NX   512
#define NH   512
#define NG   2048   // 4*H
#define NF   1024   // 2*X
#define BT   16384  // NB*NT

// fp16 GEMM tile config
#define BM   128
#define BN   128
#define BK   32
#define PITCH 40            // smem row pitch in halves (80B) -> ldmatrix conflict-free
#define LOSCALE 2048.0f
#define LOINV   (1.0f/2048.0f)
#define NSTAGE 4

// scan smem layout (in halves): Ws 64x520 (hi,lo), Hs 16x520 (hi,lo), then zbuf
#define WPITCH 520

// ---------------- device scratch (static: no allocations allowed) ----------------
__device__ __half d_xa_h[(size_t)BT * NF];         // A hi (x_g_t), fp16
__device__ __half d_w_h[(size_t)NG * NF];          // W_ih hi
__device__ __half d_w_l[(size_t)NG * NF];          // W_ih lo (x2048)
__device__ __half d_whh_h[(size_t)NG * NH];        // W_hh hi
__device__ __half d_whh_l[(size_t)NG * NH];        // W_hh lo (x2048)
__device__ __half d_hh_h[2][NB * NH];              // h ping-pong hi
__device__ __half d_hh_l[2][NB * NH];              // h ping-pong lo
__device__ float d_pre[(size_t)NT * NB * NG];      // pre-gates, [t][b][g]
__device__ float d_houts[(size_t)NT * NB * NH];    // all h_t (fp32, for BN)
__device__ float d_scaleArr[NT];
__device__ float d_shiftArr[NT];
__device__ unsigned d_flag[128 * 32];              // per-CTA generation flags, 128B apart

// ---------------- mma / ldmatrix helpers ----------------
__device__ __forceinline__ uint32_t smem_u32(const void* p) {
    uint32_t a;
    asm("{ .reg .u64 t; cvta.to.shared.u64 t, %1; cvt.u32.u64 %0, t; }" : "=r"(a) : "l"(p));
    return a;
}
__device__ __forceinline__ void ldsm4(uint32_t* r, uint32_t addr) {
    asm volatile("ldmatrix.sync.aligned.m8n8.x4.shared.b16 {%0,%1,%2,%3}, [%4];"
                 : "=r"(r[0]), "=r"(r[1]), "=r"(r[2]), "=r"(r[3]) : "r"(addr));
}
__device__ __forceinline__ void ldsm2(uint32_t* r, uint32_t addr) {
    asm volatile("ldmatrix.sync.aligned.m8n8.x2.shared.b16 {%0,%1}, [%2];"
                 : "=r"(r[0]), "=r"(r[1]) : "r"(addr));
}
__device__ __forceinline__ void mma16(float* c, const uint32_t* a, uint32_t b0, uint32_t b1) {
    asm volatile(
        "mma.sync.aligned.m16n8k16.row.col.f32.f16.f16.f32 "
        "{%0,%1,%2,%3}, {%4,%5,%6,%7}, {%8,%9}, {%0,%1,%2,%3};"
        : "+f"(c[0]), "+f"(c[1]), "+f"(c[2]), "+f"(c[3])
        : "r"(a[0]), "r"(a[1]), "r"(a[2]), "r"(a[3]), "r"(b0), "r"(b1));
}
__device__ __forceinline__ void cp16(uint32_t dst, const void* src) {
    asm volatile("cp.async.cg.shared.global [%0], [%1], 16;" :: "r"(dst), "l"(src) : "memory");
}

// ---------------- kernel 1: build x_g_t (fp16 hi only) ----------------
__global__ __launch_bounds__(256) void prep_kernel(const float* __restrict__ x) {
    int idx = blockIdx.x * blockDim.x + threadIdx.x;
    int f4 = idx & 255;
    int bt = idx >> 8;
    if (bt >= BT) return;
    int f = f4 * 4;
    const float* xb = x + (size_t)bt * (NK * NX);
    float4 v;
    if (f < NX) {
        v = *(const float4*)(xb + f);
    } else {
        int xr = f - NX;
        float4 a1 = *(const float4*)(xb + 1 * NX + xr);
        float4 a2 = *(const float4*)(xb + 2 * NX + xr);
        float4 a3 = *(const float4*)(xb + 3 * NX + xr);
        float4 a4 = *(const float4*)(xb + 4 * NX + xr);
        v.x = (a1.x + a2.x + a3.x + a4.x) * 0.25f;
        v.y = (a1.y + a2.y + a3.y + a4.y) * 0.25f;
        v.z = (a1.z + a2.z + a3.z + a4.z) * 0.25f;
        v.w = (a1.w + a2.w + a3.w + a4.w) * 0.25f;
    }
    __half2* ph = (__half2*)&d_xa_h[(size_t)bt * NF + f];
    ph[0] = __halves2half2(__float2half_rn(v.x), __float2half_rn(v.y));
    ph[1] = __halves2half2(__float2half_rn(v.z), __float2half_rn(v.w));
}

// ---------------- kernel 1b: convert W_ih to hi/lo fp16 ----------------
__global__ __launch_bounds__(256) void wconv_kernel(const float* __restrict__ Wih) {
    int idx = (blockIdx.x * 256 + threadIdx.x) * 4;
    float4 v = *(const float4*)(Wih + idx);
    __half hx = __float2half_rn(v.x), hy = __float2half_rn(v.y);
    __half hz = __float2half_rn(v.z), hw = __float2half_rn(v.w);
    __half lx = __float2half_rn((v.x - __half2float(hx)) * LOSCALE);
    __half ly = __float2half_rn((v.y - __half2float(hy)) * LOSCALE);
    __half lz = __float2half_rn((v.z - __half2float(hz)) * LOSCALE);
    __half lw = __float2half_rn((v.w - __half2float(hw)) * LOSCALE);
    __half2* ph = (__half2*)&d_w_h[idx];
    __half2* pl = (__half2*)&d_w_l[idx];
    ph[0] = __halves2half2(hx, hy); ph[1] = __halves2half2(hz, hw);
    pl[0] = __halves2half2(lx, ly); pl[1] = __halves2half2(lz, lw);
}

// ---------------- kernel 1c: convert W_hh to hi/lo fp16 ----------------
__global__ __launch_bounds__(256) void whhconv_kernel(const float* __restrict__ Whh) {
    int idx = (blockIdx.x * 256 + threadIdx.x) * 4;   // over NG*NH
    float4 v = *(const float4*)(Whh + idx);
    __half hx = __float2half_rn(v.x), hy = __float2half_rn(v.y);
    __half hz = __float2half_rn(v.z), hw = __float2half_rn(v.w);
    __half lx = __float2half_rn((v.x - __half2float(hx)) * LOSCALE);
    __half ly = __float2half_rn((v.y - __half2float(hy)) * LOSCALE);
    __half lz = __float2half_rn((v.z - __half2float(hz)) * LOSCALE);
    __half lw = __float2half_rn((v.w - __half2float(hw)) * LOSCALE);
    __half2* ph = (__half2*)&d_whh_h[idx];
    __half2* pl = (__half2*)&d_whh_l[idx];
    ph[0] = __halves2half2(hx, hy); ph[1] = __halves2half2(hz, hw);
    pl[0] = __halves2half2(lx, ly); pl[1] = __halves2half2(lz, lw);
}

// ---------------- kernel 2: fp16x2 tensor-core GEMM, 4-stage cp.async ----------------
// pre = xg_hi @ (Wih_hi + Wih_lo/2048)^T + bias.  M=16384, N=2048, K=1024.
// Per stage: A-hi (128x32) + B-hi (128x32) + B-lo (128x32).
__global__ __launch_bounds__(256, 1) void gemm16_kernel(const float* __restrict__ bih,
                                                        const float* __restrict__ bhh) {
    extern __shared__ __half hsm[];
    const uint32_t sbase = smem_u32(hsm);
    const int MAT   = BM * PITCH;    // 5120 halves per matrix
    const int STG_H = 3 * MAT;       // halves per stage

    const int tid = threadIdx.x;
    const int wid = tid >> 5;
    const int lid = tid & 31;
    const int g   = lid >> 2;
    const int tig = lid & 3;
    const int warpM = wid >> 1;
    const int warpN = wid & 1;
    const int ntile = blockIdx.x;
    const int mtile = blockIdx.y;

    float accH[2][8][4], accC[2][8][4];
#pragma unroll
    for (int i = 0; i < 2; i++)
#pragma unroll
        for (int j = 0; j < 8; j++)
#pragma unroll
            for (int q = 0; q < 4; q++) { accH[i][j][q] = 0.f; accC[i][j][q] = 0.f; }

    // 1536 16B-segments per stage, 6 per thread: mat = c>>9 (0:Ah 1:Bh 2:Bl)
    auto prefetch = [&](int i) {
        const int k0 = i * BK;
        const uint32_t sb = sbase + (uint32_t)((i & (NSTAGE - 1)) * STG_H) * 2;
#pragma unroll
        for (int j = 0; j < 6; j++) {
            int c = tid + j * 256;
            int mat = c >> 9, rem = c & 511;
            int row = rem >> 2, part = rem & 3;
            const __half* src;
            if (mat == 0)      src = d_xa_h + (size_t)(mtile * BM + row) * NF;
            else if (mat == 1) src = d_w_h + (size_t)(ntile * BN + row) * NF;
            else               src = d_w_l + (size_t)(ntile * BN + row) * NF;
            cp16(sb + (uint32_t)(mat * MAT + row * PITCH + part * 8) * 2, src + k0 + part * 8);
        }
        asm volatile("cp.async.commit_group;" ::: "memory");
    };

    prefetch(0); prefetch(1); prefetch(2);
    for (int i = 0; i < NF / BK; i++) {
        if (i <= 29)      asm volatile("cp.async.wait_group 2;" ::: "memory");
        else if (i == 30) asm volatile("cp.async.wait_group 1;" ::: "memory");
        else              asm volatile("cp.async.wait_group 0;" ::: "memory");
        __syncthreads();
        if (i < 29) prefetch(i + 3);

        const uint32_t boff = sbase + (uint32_t)((i & (NSTAGE - 1)) * STG_H) * 2;
#pragma unroll
        for (int ks = 0; ks < 2; ks++) {
            uint32_t ah[2][4];
            {
                int arow = (lid & 7) + ((lid >> 3) & 1) * 8;
                int akc = ks * 16 + (lid >> 4) * 8;
#pragma unroll
                for (int mf = 0; mf < 2; mf++) {
                    int row = warpM * 32 + mf * 16 + arow;
                    ldsm4(ah[mf], boff + (uint32_t)(row * PITCH + akc) * 2);
                }
            }
            int brow0 = (lid & 7) + ((lid >> 4) & 1) * 8;
            int bkc = ks * 16 + ((lid >> 3) & 1) * 8;
#pragma unroll
            for (int p = 0; p < 4; p++) {
                int row = warpN * 64 + p * 16 + brow0;
                uint32_t b0 = boff + (uint32_t)(MAT + row * PITCH + bkc) * 2;
                uint32_t bh[4], bl[4];
                ldsm4(bh, b0);
                ldsm4(bl, b0 + (uint32_t)MAT * 2);
#pragma unroll
                for (int mf = 0; mf < 2; mf++) {
                    mma16(accH[mf][2 * p],     ah[mf], bh[0], bh[1]);
                    mma16(accC[mf][2 * p],     ah[mf], bl[0], bl[1]);
                    mma16(accH[mf][2 * p + 1], ah[mf], bh[2], bh[3]);
                    mma16(accC[mf][2 * p + 1], ah[mf], bl[2], bl[3]);
                }
            }
        }
    }

    // epilogue: combine, add bias, scatter to pre[t][b][g]
#pragma unroll
    for (int nf = 0; nf < 8; nf++) {
        int n = ntile * BN + warpN * 64 + nf * 8 + tig * 2;
        float bias0 = bih[n] + bhh[n];
        float bias1 = bih[n + 1] + bhh[n + 1];
#pragma unroll
        for (int mf = 0; mf < 2; mf++) {
            int m0 = mtile * BM + warpM * 32 + mf * 16 + g;
            int m1 = m0 + 8;
            {
                int b = m0 >> 8, t = m0 & 255;
                float2 v = make_float2(accH[mf][nf][0] + accC[mf][nf][0] * LOINV + bias0,
                                       accH[mf][nf][1] + accC[mf][nf][1] * LOINV + bias1);
                *(float2*)&d_pre[((size_t)t * NB + b) * NG + n] = v;
            }
            {
                int b = m1 >> 8, t = m1 & 255;
                float2 v = make_float2(accH[mf][nf][2] + accC[mf][nf][2] * LOINV + bias0,
                                       accH[mf][nf][3] + accC[mf][nf][3] * LOINV + bias1);
                *(float2*)&d_pre[((size_t)t * NB + b) * NG + n] = v;
            }
        }
    }
}

// ---------------- kernel 3: tensor-core persistent scan ----------------
// 128 CTAs (hg 0..31 x bg 0..3), 512 threads. Per-thread fine-grained flag waits:
// each staging thread polls only the producer CTA of its h-slice.
__global__ __launch_bounds__(512) void scan_kernel() {
    extern __shared__ char smraw[];
    __half* WsH = (__half*)smraw;                 // 64 x 520
    __half* WsL = WsH + 64 * WPITCH;
    __half* HsH = WsL + 64 * WPITCH;              // 16 x 520
    __half* HsL = HsH + 16 * WPITCH;
    float*  zb  = (float*)(HsL + 16 * WPITCH);    // 2 x 64 x 17
    unsigned* sbase_p = (unsigned*)(zb + 2 * 64 * 17);

    const int tid = threadIdx.x;
    const int cid = blockIdx.x;
    const int hg = cid & 31;
    const int bg = cid >> 5;

    if (tid == 0) {
        unsigned b;
        asm volatile("ld.acquire.gpu.global.u32 %0, [%1];" : "=r"(b) : "l"(&d_flag[cid * 32]) : "memory");
        *sbase_p = b;
    }

    // load W_hh slice hi/lo: rows r=q*16+cs -> gate G = q*512 + hg*16 + cs
    for (int i = tid; i < 4096; i += 512) {
        int r = i >> 6, k8 = (i & 63) * 8;
        int G = (r >> 4) * NH + hg * 16 + (r & 15);
        *(uint4*)&WsH[r * WPITCH + k8] = *(const uint4*)&d_whh_h[(size_t)G * NH + k8];
        *(uint4*)&WsL[r * WPITCH + k8] = *(const uint4*)&d_whh_l[(size_t)G * NH + k8];
    }
    // zero h staging (h_{-1} = 0)
    for (int i = tid; i < 2080; i += 512) {
        ((uint4*)HsH)[i] = make_uint4(0u, 0u, 0u, 0u);
    }
    __syncthreads();
    const unsigned base = *sbase_p;

    // matvec warp mapping: 16 warps = 4(m) x 2(n) x 2(k-half)
    const int lid = tid & 31;
    const int wid = tid >> 5;
    const int kh = wid >> 3;
    const int w8 = wid & 7;
    const int mq = w8 & 3;
    const int nq = w8 >> 2;
    const uint32_t sb32 = smem_u32(smraw);
    const int arow = mq * 16 + (lid & 7) + ((lid >> 3) & 1) * 8;
    const uint32_t a_base = sb32 + (uint32_t)(arow * WPITCH + (lid >> 4) * 8 + kh * 256) * 2;
    const uint32_t ALO = (uint32_t)(64 * WPITCH) * 2;
    const int brow = nq * 8 + (lid & 7);
    const uint32_t b_base = sb32 + (uint32_t)(128 * WPITCH) * 2
                          + (uint32_t)(brow * WPITCH + ((lid >> 3) & 1) * 8 + kh * 256) * 2;
    const uint32_t BLO = (uint32_t)(16 * WPITCH) * 2;

    // cell mapping (tid < 256)
    const int colsub = tid & 15;
    const int bsub = (tid >> 4) & 15;
    const int col = hg * 16 + colsub;
    const int bb = bg * 16 + bsub;
    float c = 0.f;

    // staging slice: cols [k8s, k8s+8) for batches sb0 and sb0+8 -> one producer CTA
    const int k8s = (tid & 63) * 8;
    const int sb0 = tid >> 6;                        // 0..7
    const unsigned* myflag = &d_flag[(bg * 32 + ((tid & 63) >> 1)) * 32];

    for (int t = 0; t < NT; t++) {
        // prefetch pre-gate values (overlaps flag wait + staging)
        float pv0 = 0.f, pv1 = 0.f, pv2 = 0.f, pv3 = 0.f;
        if (tid < 256) {
            const float* pr = d_pre + ((size_t)t * NB + bb) * NG + col;
            pv0 = pr[0]; pv1 = pr[512]; pv2 = pr[1024]; pv3 = pr[1536];
        }
        if (t > 0) {
            unsigned target = base + (unsigned)t;
            unsigned v;
            do {
                asm volatile("ld.acquire.gpu.global.u32 %0, [%1];" : "=r"(v) : "l"(myflag) : "memory");
            } while ((int)(v - target) < 0);
            const __half* srcH = d_hh_h[(t + 1) & 1];
            const __half* srcL = d_hh_l[(t + 1) & 1];
            *(uint4*)&HsH[sb0 * WPITCH + k8s]       = *(const uint4*)&srcH[(bg * 16 + sb0) * NH + k8s];
            *(uint4*)&HsH[(sb0 + 8) * WPITCH + k8s] = *(const uint4*)&srcH[(bg * 16 + sb0 + 8) * NH + k8s];
            *(uint4*)&HsL[sb0 * WPITCH + k8s]       = *(const uint4*)&srcL[(bg * 16 + sb0) * NH + k8s];
            *(uint4*)&HsL[(sb0 + 8) * WPITCH + k8s] = *(const uint4*)&srcL[(bg * 16 + sb0 + 8) * NH + k8s];
        }
        __syncthreads();

        // matvec: 16 k-steps of k16 per warp (fp16 hi/lo x3 — full precision kept here)
        float aH[4] = {0, 0, 0, 0}, aC1[4] = {0, 0, 0, 0}, aC2[4] = {0, 0, 0, 0};
        uint32_t aaddr = a_base, baddr = b_base;
#pragma unroll
        for (int kk = 0; kk < 16; kk++) {
            uint32_t ah[4], al[4], bh[2], bl[2];
            ldsm4(ah, aaddr);
            ldsm4(al, aaddr + ALO);
            ldsm2(bh, baddr);
            ldsm2(bl, baddr + BLO);
            mma16(aH,  ah, bh[0], bh[1]);
            mma16(aC1, ah, bl[0], bl[1]);
            mma16(aC2, al, bh[0], bh[1]);
            aaddr += 32; baddr += 32;
        }
        {
            float* z = zb + kh * (64 * 17);
            int zr = mq * 16 + (lid >> 2);
            int zc = nq * 8 + (lid & 3) * 2;
            z[zr * 17 + zc]           = aH[0] + (aC1[0] + aC2[0]) * LOINV;
            z[zr * 17 + zc + 1]       = aH[1] + (aC1[1] + aC2[1]) * LOINV;
            z[(zr + 8) * 17 + zc]     = aH[2] + (aC1[2] + aC2[2]) * LOINV;
            z[(zr + 8) * 17 + zc + 1] = aH[3] + (aC1[3] + aC2[3]) * LOINV;
        }
        __syncthreads();

        float hv = 0.f;
        if (tid < 256) {
            float zi = zb[(0 * 16 + colsub) * 17 + bsub] + zb[64 * 17 + (0 * 16 + colsub) * 17 + bsub] + pv0;
            float zf = zb[(1 * 16 + colsub) * 17 + bsub] + zb[64 * 17 + (1 * 16 + colsub) * 17 + bsub] + pv1;
            float zg = zb[(2 * 16 + colsub) * 17 + bsub] + zb[64 * 17 + (2 * 16 + colsub) * 17 + bsub] + pv2;
            float zo = zb[(3 * 16 + colsub) * 17 + bsub] + zb[64 * 17 + (3 * 16 + colsub) * 17 + bsub] + pv3;
            float ig = 1.f / (1.f + expf(-zi));
            float fg = 1.f / (1.f + expf(-zf));
            float gg = tanhf(zg);
            float og = 1.f / (1.f + expf(-zo));
            c = fg * c + ig * gg;
            hv = og * tanhf(c);
            __half hh = __float2half_rn(hv);
            __half hl = __float2half_rn((hv - __half2float(hh)) * LOSCALE);
            d_hh_h[t & 1][bb * NH + col] = hh;
            d_hh_l[t & 1][bb * NH + col] = hl;
        }
        __syncthreads();
        if (tid == 0) {
            asm volatile("st.release.gpu.global.u32 [%0], %1;"
                         :: "l"(&d_flag[cid * 32]), "r"(base + (unsigned)t + 1u) : "memory");
        }
        // DRAM store after the release so the fence doesn't drain it
        if (tid < 256) {
            d_houts[(size_t)t * (NB * NH) + bb * NH + col] = hv;
        }
    }
}

// ---------------- kernel 4: per-t BN stats -> scale/shift ----------------
__global__ __launch_bounds__(256) void stats_kernel(const float* __restrict__ gamma,
                                                    const float* __restrict__ beta) {
    int t = blockIdx.x;
    const float4* p = (const float4*)(d_houts + (size_t)t * (NB * NH));
    float s = 0.f, ss = 0.f;
    for (int i = threadIdx.x; i < (NB * NH) / 4; i += 256) {
        float4 v = p[i];
        s  += v.x + v.y + v.z + v.w;
        ss += v.x * v.x + v.y * v.y + v.z * v.z + v.w * v.w;
    }
#pragma unroll
    for (int o = 16; o > 0; o >>= 1) {
        s  += __shfl_down_sync(0xffffffffu, s, o);
        ss += __shfl_down_sync(0xffffffffu, ss, o);
    }
    __shared__ float rs[8], rss[8];
    int w = threadIdx.x >> 5;
    if ((threadIdx.x & 31) == 0) { rs[w] = s; rss[w] = ss; }
    __syncthreads();
    if (threadIdx.x == 0) {
        float S = 0.f, SS = 0.f;
#pragma unroll
        for (int i = 0; i < 8; i++) { S += rs[i]; SS += rss[i]; }
        float mean = S * (1.f / (NB * NH));
        float var = SS * (1.f / (NB * NH)) - mean * mean;
        float sc = gamma[t] * rsqrtf(var + 1e-5f);
        d_scaleArr[t] = sc;
        d_shiftArr[t] = beta[t] - mean * sc;
    }
}

// ---------------- kernel 5: elu(BN(h)) mean over t -> out[b][h] ----------------
__global__ __launch_bounds__(256) void final_kernel(float* __restrict__ out) {
    int idx = blockIdx.x * 256 + threadIdx.x;
    float acc = 0.f;
#pragma unroll 4
    for (int t = 0; t < NT; t++) {
        float v = d_houts[(size_t)t * (NB * NH) + idx];
        float u = v * d_scaleArr[t] + d_shiftArr[t];
        acc += (u > 0.f) ? u : expm1f(u);
    }
    out[idx] = acc * (1.f / NT);
}

// ---------------- launch ----------------
extern "C" void kernel_launch(void* const* d_in, const int* in_sizes, int n_in,
                              void* d_out, int out_size) {
    const float* x     = (const float*)d_in[0];
    const float* Wih   = (const float*)d_in[1];
    const float* Whh   = (const float*)d_in[2];
    const float* bih   = (const float*)d_in[3];
    const float* bhh   = (const float*)d_in[4];
    const float* gamma = (const float*)d_in[5];
    const float* beta  = (const float*)d_in[6];
    float* out = (float*)d_out;

    prep_kernel<<<BT, 256>>>(x);
    wconv_kernel<<<(NG * NF / 4) / 256, 256>>>(Wih);
    whhconv_kernel<<<(NG * NH / 4) / 256, 256>>>(Whh);

    int gsmem = NSTAGE * 3 * BM * PITCH * 2;   // 122,880 B (4-stage, 3 matrices)
    cudaFuncSetAttribute(gemm16_kernel, cudaFuncAttributeMaxDynamicSharedMemorySize, gsmem);
    dim3 ggrid(NG / BN, BT / BM);              // (16, 128)
    gemm16_kernel<<<ggrid, 256, gsmem>>>(bih, bhh);

    int ssmem = (64 * WPITCH + 64 * WPITCH + 16 * WPITCH + 16 * WPITCH) * 2
              + 2 * 64 * 17 * 4 + 16;          // 175,120 B
    cudaFuncSetAttribute(scan_kernel, cudaFuncAttributeMaxDynamicSharedMemorySize, ssmem);
    scan_kernel<<<128, 512, ssmem>>>();

    stats_kernel<<<NT, 256>>>(gamma, beta);
    final_kernel<<<(NB * NH) / 256, 256>>>(out);
}

// round 9
// speedup vs baseline: 3.8451x; 1.1301x over previous
#include <cuda_runtime.h>
#include <cuda_fp16.h>
#include <cstdint>
#include <math.h>

// Problem constants
#define NB   64     // batch
#define NT   256    // time
#define NK   5
#define NX   512
#define NH   512
#define NG   2048   // 4*H
#define NF   1024   // 2*X
#define BT   16384  // NB*NT

// fp16 GEMM tile config
#define BM   128
#define BN   128
#define BK   32
#define PITCH 40            // smem row pitch in halves (80B) -> ldmatrix conflict-free
#define LOSCALE 2048.0f
#define LOINV   (1.0f/2048.0f)
#define NSTAGE 4

// scan smem layout (in halves): WsH 64x520, WsL 64x520, HsH 16x520, then zbuf
#define WPITCH 520

// ---------------- device scratch (static: no allocations allowed) ----------------
__device__ __half d_xa_h[(size_t)BT * NF];         // A hi (x_g_t), fp16
__device__ __half d_w_h[(size_t)NG * NF];          // W_ih hi
__device__ __half d_w_l[(size_t)NG * NF];          // W_ih lo (x2048)
__device__ __half d_whh_h[(size_t)NG * NH];        // W_hh hi
__device__ __half d_whh_l[(size_t)NG * NH];        // W_hh lo (x2048)
__device__ __half d_hh_h[2][NB * NH];              // h ping-pong (fp16)
__device__ float d_pre[(size_t)NT * NB * NG];      // pre-gates, [t][b][g]
__device__ float d_houts[(size_t)NT * NB * NH];    // all h_t (fp32, for BN)
__device__ float d_scaleArr[NT];
__device__ float d_shiftArr[NT];
__device__ unsigned d_flag[128 * 32];              // per-CTA generation flags, 128B apart

// ---------------- mma / ldmatrix helpers ----------------
__device__ __forceinline__ uint32_t smem_u32(const void* p) {
    uint32_t a;
    asm("{ .reg .u64 t; cvta.to.shared.u64 t, %1; cvt.u32.u64 %0, t; }" : "=r"(a) : "l"(p));
    return a;
}
__device__ __forceinline__ void ldsm4(uint32_t* r, uint32_t addr) {
    asm volatile("ldmatrix.sync.aligned.m8n8.x4.shared.b16 {%0,%1,%2,%3}, [%4];"
                 : "=r"(r[0]), "=r"(r[1]), "=r"(r[2]), "=r"(r[3]) : "r"(addr));
}
__device__ __forceinline__ void ldsm2(uint32_t* r, uint32_t addr) {
    asm volatile("ldmatrix.sync.aligned.m8n8.x2.shared.b16 {%0,%1}, [%2];"
                 : "=r"(r[0]), "=r"(r[1]) : "r"(addr));
}
__device__ __forceinline__ void mma16(float* c, const uint32_t* a, uint32_t b0, uint32_t b1) {
    asm volatile(
        "mma.sync.aligned.m16n8k16.row.col.f32.f16.f16.f32 "
        "{%0,%1,%2,%3}, {%4,%5,%6,%7}, {%8,%9}, {%0,%1,%2,%3};"
        : "+f"(c[0]), "+f"(c[1]), "+f"(c[2]), "+f"(c[3])
        : "r"(a[0]), "r"(a[1]), "r"(a[2]), "r"(a[3]), "r"(b0), "r"(b1));
}
__device__ __forceinline__ void cp16(uint32_t dst, const void* src) {
    asm volatile("cp.async.cg.shared.global [%0], [%1], 16;" :: "r"(dst), "l"(src) : "memory");
}

// ---------------- kernel 1: build x_g_t (fp16 hi only) ----------------
__global__ __launch_bounds__(256) void prep_kernel(const float* __restrict__ x) {
    int idx = blockIdx.x * blockDim.x + threadIdx.x;
    int f4 = idx & 255;
    int bt = idx >> 8;
    if (bt >= BT) return;
    int f = f4 * 4;
    const float* xb = x + (size_t)bt * (NK * NX);
    float4 v;
    if (f < NX) {
        v = *(const float4*)(xb + f);
    } else {
        int xr = f - NX;
        float4 a1 = *(const float4*)(xb + 1 * NX + xr);
        float4 a2 = *(const float4*)(xb + 2 * NX + xr);
        float4 a3 = *(const float4*)(xb + 3 * NX + xr);
        float4 a4 = *(const float4*)(xb + 4 * NX + xr);
        v.x = (a1.x + a2.x + a3.x + a4.x) * 0.25f;
        v.y = (a1.y + a2.y + a3.y + a4.y) * 0.25f;
        v.z = (a1.z + a2.z + a3.z + a4.z) * 0.25f;
        v.w = (a1.w + a2.w + a3.w + a4.w) * 0.25f;
    }
    __half2* ph = (__half2*)&d_xa_h[(size_t)bt * NF + f];
    ph[0] = __halves2half2(__float2half_rn(v.x), __float2half_rn(v.y));
    ph[1] = __halves2half2(__float2half_rn(v.z), __float2half_rn(v.w));
}

// ---------------- kernel 1b: convert W_ih to hi/lo fp16 ----------------
__global__ __launch_bounds__(256) void wconv_kernel(const float* __restrict__ Wih) {
    int idx = (blockIdx.x * 256 + threadIdx.x) * 4;
    float4 v = *(const float4*)(Wih + idx);
    __half hx = __float2half_rn(v.x), hy = __float2half_rn(v.y);
    __half hz = __float2half_rn(v.z), hw = __float2half_rn(v.w);
    __half lx = __float2half_rn((v.x - __half2float(hx)) * LOSCALE);
    __half ly = __float2half_rn((v.y - __half2float(hy)) * LOSCALE);
    __half lz = __float2half_rn((v.z - __half2float(hz)) * LOSCALE);
    __half lw = __float2half_rn((v.w - __half2float(hw)) * LOSCALE);
    __half2* ph = (__half2*)&d_w_h[idx];
    __half2* pl = (__half2*)&d_w_l[idx];
    ph[0] = __halves2half2(hx, hy); ph[1] = __halves2half2(hz, hw);
    pl[0] = __halves2half2(lx, ly); pl[1] = __halves2half2(lz, lw);
}

// ---------------- kernel 1c: convert W_hh to hi/lo fp16 ----------------
__global__ __launch_bounds__(256) void whhconv_kernel(const float* __restrict__ Whh) {
    int idx = (blockIdx.x * 256 + threadIdx.x) * 4;   // over NG*NH
    float4 v = *(const float4*)(Whh + idx);
    __half hx = __float2half_rn(v.x), hy = __float2half_rn(v.y);
    __half hz = __float2half_rn(v.z), hw = __float2half_rn(v.w);
    __half lx = __float2half_rn((v.x - __half2float(hx)) * LOSCALE);
    __half ly = __float2half_rn((v.y - __half2float(hy)) * LOSCALE);
    __half lz = __float2half_rn((v.z - __half2float(hz)) * LOSCALE);
    __half lw = __float2half_rn((v.w - __half2float(hw)) * LOSCALE);
    __half2* ph = (__half2*)&d_whh_h[idx];
    __half2* pl = (__half2*)&d_whh_l[idx];
    ph[0] = __halves2half2(hx, hy); ph[1] = __halves2half2(hz, hw);
    pl[0] = __halves2half2(lx, ly); pl[1] = __halves2half2(lz, lw);
}

// ---------------- kernel 2: fp16x2 tensor-core GEMM, 4-stage cp.async, B-frag pipelined ----------------
__global__ __launch_bounds__(256, 1) void gemm16_kernel(const float* __restrict__ bih,
                                                        const float* __restrict__ bhh) {
    extern __shared__ __half hsm[];
    const uint32_t sbase = smem_u32(hsm);
    const int MAT   = BM * PITCH;    // 5120 halves per matrix
    const int STG_H = 3 * MAT;       // halves per stage

    const int tid = threadIdx.x;
    const int wid = tid >> 5;
    const int lid = tid & 31;
    const int g   = lid >> 2;
    const int tig = lid & 3;
    const int warpM = wid >> 1;
    const int warpN = wid & 1;
    const int ntile = blockIdx.x;
    const int mtile = blockIdx.y;

    float accH[2][8][4], accC[2][8][4];
#pragma unroll
    for (int i = 0; i < 2; i++)
#pragma unroll
        for (int j = 0; j < 8; j++)
#pragma unroll
            for (int q = 0; q < 4; q++) { accH[i][j][q] = 0.f; accC[i][j][q] = 0.f; }

    auto prefetch = [&](int i) {
        const int k0 = i * BK;
        const uint32_t sb = sbase + (uint32_t)((i & (NSTAGE - 1)) * STG_H) * 2;
#pragma unroll
        for (int j = 0; j < 6; j++) {
            int c = tid + j * 256;
            int mat = c >> 9, rem = c & 511;
            int row = rem >> 2, part = rem & 3;
            const __half* src;
            if (mat == 0)      src = d_xa_h + (size_t)(mtile * BM + row) * NF;
            else if (mat == 1) src = d_w_h + (size_t)(ntile * BN + row) * NF;
            else               src = d_w_l + (size_t)(ntile * BN + row) * NF;
            cp16(sb + (uint32_t)(mat * MAT + row * PITCH + part * 8) * 2, src + k0 + part * 8);
        }
        asm volatile("cp.async.commit_group;" ::: "memory");
    };

    prefetch(0); prefetch(1); prefetch(2);
    for (int i = 0; i < NF / BK; i++) {
        if (i <= 29)      asm volatile("cp.async.wait_group 2;" ::: "memory");
        else if (i == 30) asm volatile("cp.async.wait_group 1;" ::: "memory");
        else              asm volatile("cp.async.wait_group 0;" ::: "memory");
        __syncthreads();
        if (i < 29) prefetch(i + 3);

        const uint32_t boff = sbase + (uint32_t)((i & (NSTAGE - 1)) * STG_H) * 2;
#pragma unroll
        for (int ks = 0; ks < 2; ks++) {
            uint32_t ah[2][4];
            {
                int arow = (lid & 7) + ((lid >> 3) & 1) * 8;
                int akc = ks * 16 + (lid >> 4) * 8;
#pragma unroll
                for (int mf = 0; mf < 2; mf++) {
                    int row = warpM * 32 + mf * 16 + arow;
                    ldsm4(ah[mf], boff + (uint32_t)(row * PITCH + akc) * 2);
                }
            }
            int brow0 = (lid & 7) + ((lid >> 4) & 1) * 8;
            int bkc = ks * 16 + ((lid >> 3) & 1) * 8;
            // register double-buffer B fragments: load p+1 before p's mmas
            uint32_t bh[2][4], bl[2][4];
            {
                int row = warpN * 64 + brow0;
                uint32_t b0 = boff + (uint32_t)(MAT + row * PITCH + bkc) * 2;
                ldsm4(bh[0], b0);
                ldsm4(bl[0], b0 + (uint32_t)MAT * 2);
            }
#pragma unroll
            for (int p = 0; p < 4; p++) {
                int cur = p & 1, nxt = cur ^ 1;
                if (p < 3) {
                    int row = warpN * 64 + (p + 1) * 16 + brow0;
                    uint32_t b0 = boff + (uint32_t)(MAT + row * PITCH + bkc) * 2;
                    ldsm4(bh[nxt], b0);
                    ldsm4(bl[nxt], b0 + (uint32_t)MAT * 2);
                }
#pragma unroll
                for (int mf = 0; mf < 2; mf++) {
                    mma16(accH[mf][2 * p],     ah[mf], bh[cur][0], bh[cur][1]);
                    mma16(accC[mf][2 * p],     ah[mf], bl[cur][0], bl[cur][1]);
                    mma16(accH[mf][2 * p + 1], ah[mf], bh[cur][2], bh[cur][3]);
                    mma16(accC[mf][2 * p + 1], ah[mf], bl[cur][2], bl[cur][3]);
                }
            }
        }
    }

    // epilogue: combine, add bias, scatter to pre[t][b][g]
#pragma unroll
    for (int nf = 0; nf < 8; nf++) {
        int n = ntile * BN + warpN * 64 + nf * 8 + tig * 2;
        float bias0 = bih[n] + bhh[n];
        float bias1 = bih[n + 1] + bhh[n + 1];
#pragma unroll
        for (int mf = 0; mf < 2; mf++) {
            int m0 = mtile * BM + warpM * 32 + mf * 16 + g;
            int m1 = m0 + 8;
            {
                int b = m0 >> 8, t = m0 & 255;
                float2 v = make_float2(accH[mf][nf][0] + accC[mf][nf][0] * LOINV + bias0,
                                       accH[mf][nf][1] + accC[mf][nf][1] * LOINV + bias1);
                *(float2*)&d_pre[((size_t)t * NB + b) * NG + n] = v;
            }
            {
                int b = m1 >> 8, t = m1 & 255;
                float2 v = make_float2(accH[mf][nf][2] + accC[mf][nf][2] * LOINV + bias0,
                                       accH[mf][nf][3] + accC[mf][nf][3] * LOINV + bias1);
                *(float2*)&d_pre[((size_t)t * NB + b) * NG + n] = v;
            }
        }
    }
}

// ---------------- kernel 3: tensor-core persistent scan, split-role pipeline ----------------
// 128 CTAs (hg 0..31 x bg 0..3), 512 threads.
//   warps 0-7  (cells):   pv prefetch, matvec, gates, h store, release
//   warps 8-15 (stagers): flag wait + h staging (overlaps cells' gate phase), matvec
// matvec: z = Whh_hi@h + (Whh_lo@h)/2048  (h quantized to fp16; x2 mma)
__global__ __launch_bounds__(512) void scan_kernel() {
    extern __shared__ char smraw[];
    __half* WsH = (__half*)smraw;                 // 64 x 520
    __half* WsL = WsH + 64 * WPITCH;
    __half* HsH = WsL + 64 * WPITCH;              // 16 x 520
    float*  zb  = (float*)(HsH + 16 * WPITCH);    // 2 x 64 x 17
    unsigned* sbase_p = (unsigned*)(zb + 2 * 64 * 17);

    const int tid = threadIdx.x;
    const int cid = blockIdx.x;
    const int hg = cid & 31;
    const int bg = cid >> 5;

    if (tid == 0) {
        unsigned b;
        asm volatile("ld.acquire.gpu.global.u32 %0, [%1];" : "=r"(b) : "l"(&d_flag[cid * 32]) : "memory");
        *sbase_p = b;
    }

    // load W_hh slice hi/lo: rows r=q*16+cs -> gate G = q*512 + hg*16 + cs
    for (int i = tid; i < 4096; i += 512) {
        int r = i >> 6, k8 = (i & 63) * 8;
        int G = (r >> 4) * NH + hg * 16 + (r & 15);
        *(uint4*)&WsH[r * WPITCH + k8] = *(const uint4*)&d_whh_h[(size_t)G * NH + k8];
        *(uint4*)&WsL[r * WPITCH + k8] = *(const uint4*)&d_whh_l[(size_t)G * NH + k8];
    }
    // zero h staging (h_{-1} = 0): 16*520 halves = 1040 uint4
    for (int i = tid; i < 1040; i += 512) {
        ((uint4*)HsH)[i] = make_uint4(0u, 0u, 0u, 0u);
    }
    __syncthreads();
    const unsigned base = *sbase_p;

    // matvec warp mapping: 16 warps = 4(m) x 2(n) x 2(k-half)
    const int lid = tid & 31;
    const int wid = tid >> 5;
    const int kh = wid >> 3;
    const int w8 = wid & 7;
    const int mq = w8 & 3;
    const int nq = w8 >> 2;
    const uint32_t sb32 = smem_u32(smraw);
    const int arow = mq * 16 + (lid & 7) + ((lid >> 3) & 1) * 8;
    const uint32_t a_base = sb32 + (uint32_t)(arow * WPITCH + (lid >> 4) * 8 + kh * 256) * 2;
    const uint32_t ALO = (uint32_t)(64 * WPITCH) * 2;
    const int brow = nq * 8 + (lid & 7);
    const uint32_t b_base = sb32 + (uint32_t)(128 * WPITCH) * 2
                          + (uint32_t)(brow * WPITCH + ((lid >> 3) & 1) * 8 + kh * 256) * 2;

    // cell mapping (tid < 256)
    const int colsub = tid & 15;
    const int bsub = (tid >> 4) & 15;
    const int col = hg * 16 + colsub;
    const int bb = bg * 16 + bsub;
    float c = 0.f;

    // stager mapping (tid >= 256): col-chunk cc (8 cols), row group rg (4 rows)
    const int tp = tid & 255;
    const int cc = tp & 63;
    const int rg = tp >> 6;
    const unsigned* myflag = &d_flag[(bg * 32 + (cc >> 1)) * 32];

    for (int t = 0; t < NT; t++) {
        float pv0 = 0.f, pv1 = 0.f, pv2 = 0.f, pv3 = 0.f;
        if (tid < 256) {
            const float* pr = d_pre + ((size_t)t * NB + bb) * NG + col;
            pv0 = pr[0]; pv1 = pr[512]; pv2 = pr[1024]; pv3 = pr[1536];
        } else if (t > 0) {
            unsigned target = base + (unsigned)t;
            unsigned v;
            do {
                asm volatile("ld.acquire.gpu.global.u32 %0, [%1];" : "=r"(v) : "l"(myflag) : "memory");
            } while ((int)(v - target) < 0);
            const __half* srcH = d_hh_h[(t + 1) & 1];
#pragma unroll
            for (int j = 0; j < 4; j++) {
                int r = rg * 4 + j;
                *(uint4*)&HsH[r * WPITCH + cc * 8] = *(const uint4*)&srcH[(bg * 16 + r) * NH + cc * 8];
            }
        }
        __syncthreads();   // A: staged h visible to all matvec warps

        // matvec: 16 k-steps of k16 per warp (x2: hi + W-lo correction)
        float aH[4] = {0, 0, 0, 0}, aC[4] = {0, 0, 0, 0};
        uint32_t aaddr = a_base, baddr = b_base;
#pragma unroll
        for (int kk = 0; kk < 16; kk++) {
            uint32_t ah[4], al[4], bh[2];
            ldsm4(ah, aaddr);
            ldsm4(al, aaddr + ALO);
            ldsm2(bh, baddr);
            mma16(aH, ah, bh[0], bh[1]);
            mma16(aC, al, bh[0], bh[1]);
            aaddr += 32; baddr += 32;
        }
        {
            float* z = zb + kh * (64 * 17);
            int zr = mq * 16 + (lid >> 2);
            int zc = nq * 8 + (lid & 3) * 2;
            z[zr * 17 + zc]           = aH[0] + aC[0] * LOINV;
            z[zr * 17 + zc + 1]       = aH[1] + aC[1] * LOINV;
            z[(zr + 8) * 17 + zc]     = aH[2] + aC[2] * LOINV;
            z[(zr + 8) * 17 + zc + 1] = aH[3] + aC[3] * LOINV;
        }
        __syncthreads();   // B: zb visible to cells

        if (tid < 256) {
            float zi = zb[(0 * 16 + colsub) * 17 + bsub] + zb[64 * 17 + (0 * 16 + colsub) * 17 + bsub] + pv0;
            float zf = zb[(1 * 16 + colsub) * 17 + bsub] + zb[64 * 17 + (1 * 16 + colsub) * 17 + bsub] + pv1;
            float zg = zb[(2 * 16 + colsub) * 17 + bsub] + zb[64 * 17 + (2 * 16 + colsub) * 17 + bsub] + pv2;
            float zo = zb[(3 * 16 + colsub) * 17 + bsub] + zb[64 * 17 + (3 * 16 + colsub) * 17 + bsub] + pv3;
            float ig = 1.f / (1.f + expf(-zi));
            float fg = 1.f / (1.f + expf(-zf));
            float gg = tanhf(zg);
            float og = 1.f / (1.f + expf(-zo));
            c = fg * c + ig * gg;
            float hv = og * tanhf(c);
            d_hh_h[t & 1][bb * NH + col] = __float2half_rn(hv);
            asm volatile("bar.sync 1, 256;" ::: "memory");   // cells only
            if (tid == 0) {
                asm volatile("st.release.gpu.global.u32 [%0], %1;"
                             :: "l"(&d_flag[cid * 32]), "r"(base + (unsigned)t + 1u) : "memory");
            }
            d_houts[(size_t)t * (NB * NH) + bb * NH + col] = hv;
        }
        // stagers skip straight to next step's flag wait (overlaps cells' gate phase)
    }
}

// ---------------- kernel 4: per-t BN stats -> scale/shift ----------------
__global__ __launch_bounds__(256) void stats_kernel(const float* __restrict__ gamma,
                                                    const float* __restrict__ beta) {
    int t = blockIdx.x;
    const float4* p = (const float4*)(d_houts + (size_t)t * (NB * NH));
    float s = 0.f, ss = 0.f;
    for (int i = threadIdx.x; i < (NB * NH) / 4; i += 256) {
        float4 v = p[i];
        s  += v.x + v.y + v.z + v.w;
        ss += v.x * v.x + v.y * v.y + v.z * v.z + v.w * v.w;
    }
#pragma unroll
    for (int o = 16; o > 0; o >>= 1) {
        s  += __shfl_down_sync(0xffffffffu, s, o);
        ss += __shfl_down_sync(0xffffffffu, ss, o);
    }
    __shared__ float rs[8], rss[8];
    int w = threadIdx.x >> 5;
    if ((threadIdx.x & 31) == 0) { rs[w] = s; rss[w] = ss; }
    __syncthreads();
    if (threadIdx.x == 0) {
        float S = 0.f, SS = 0.f;
#pragma unroll
        for (int i = 0; i < 8; i++) { S += rs[i]; SS += rss[i]; }
        float mean = S * (1.f / (NB * NH));
        float var = SS * (1.f / (NB * NH)) - mean * mean;
        float sc = gamma[t] * rsqrtf(var + 1e-5f);
        d_scaleArr[t] = sc;
        d_shiftArr[t] = beta[t] - mean * sc;
    }
}

// ---------------- kernel 5: elu(BN(h)) mean over t -> out[b][h] ----------------
__global__ __launch_bounds__(256) void final_kernel(float* __restrict__ out) {
    int idx = blockIdx.x * 256 + threadIdx.x;
    float acc = 0.f;
#pragma unroll 4
    for (int t = 0; t < NT; t++) {
        float v = d_houts[(size_t)t * (NB * NH) + idx];
        float u = v * d_scaleArr[t] + d_shiftArr[t];
        acc += (u > 0.f) ? u : expm1f(u);
    }
    out[idx] = acc * (1.f / NT);
}

// ---------------- launch ----------------
extern "C" void kernel_launch(void* const* d_in, const int* in_sizes, int n_in,
                              void* d_out, int out_size) {
    const float* x     = (const float*)d_in[0];
    const float* Wih   = (const float*)d_in[1];
    const float* Whh   = (const float*)d_in[2];
    const float* bih   = (const float*)d_in[3];
    const float* bhh   = (const float*)d_in[4];
    const float* gamma = (const float*)d_in[5];
    const float* beta  = (const float*)d_in[6];
    float* out = (float*)d_out;

    prep_kernel<<<BT, 256>>>(x);
    wconv_kernel<<<(NG * NF / 4) / 256, 256>>>(Wih);
    whhconv_kernel<<<(NG * NH / 4) / 256, 256>>>(Whh);

    int gsmem = NSTAGE * 3 * BM * PITCH * 2;   // 122,880 B
    cudaFuncSetAttribute(gemm16_kernel, cudaFuncAttributeMaxDynamicSharedMemorySize, gsmem);
    dim3 ggrid(NG / BN, BT / BM);              // (16, 128)
    gemm16_kernel<<<ggrid, 256, gsmem>>>(bih, bhh);

    int ssmem = (64 * WPITCH + 64 * WPITCH + 16 * WPITCH) * 2
              + 2 * 64 * 17 * 4 + 16;          // 158,480 B
    cudaFuncSetAttribute(scan_kernel, cudaFuncAttributeMaxDynamicSharedMemorySize, ssmem);
    scan_kernel<<<128, 512, ssmem>>>();

    stats_kernel<<<NT, 256>>>(gamma, beta);
    final_kernel<<<(NB * NH) / 256, 256>>>(out);
}

// round 10
// speedup vs baseline: 3.8545x; 1.0025x over previous
#include <cuda_runtime.h>
#include <cuda_fp16.h>
#include <cstdint>
#include <math.h>

// Problem constants
#define NB   64     // batch
#define NT   256    // time
#define NK   5
#define NX   512
#define NH   512
#define NG   2048   // 4*H
#define NF   1024   // 2*X
#define BT   16384  // NB*NT

// fp16 GEMM tile config
#define BM   128
#define BN   128
#define BK   32
#define PITCH 40            // smem row pitch in halves (80B) -> ldmatrix conflict-free
#define LOSCALE 2048.0f
#define LOINV   (1.0f/2048.0f)
#define NSTAGE 4

// scan smem layout (in halves): WsH 64x520, WsL 64x520, HsH 16x520, then zbuf
#define WPITCH 520

// ---------------- device scratch (static: no allocations allowed) ----------------
__device__ __half d_xa_h[(size_t)BT * NF];         // A hi (x_g_t), fp16
__device__ __half d_w_h[(size_t)NG * NF];          // W_ih hi
__device__ __half d_w_l[(size_t)NG * NF];          // W_ih lo (x2048)
__device__ __half d_whh_h[(size_t)NG * NH];        // W_hh hi
__device__ __half d_whh_l[(size_t)NG * NH];        // W_hh lo (x2048)
__device__ __half d_hh_h[2][NB * NH];              // h ping-pong (fp16)
__device__ float d_pre[(size_t)NT * NB * NG];      // pre-gates, [t][b][g]
__device__ float d_houts[(size_t)NT * NB * NH];    // all h_t (fp32, for BN)
__device__ float d_scaleArr[NT];
__device__ float d_shiftArr[NT];
__device__ unsigned d_flag[128 * 32];              // per-CTA generation flags, 128B apart

// ---------------- mma / ldmatrix helpers ----------------
__device__ __forceinline__ uint32_t smem_u32(const void* p) {
    uint32_t a;
    asm("{ .reg .u64 t; cvta.to.shared.u64 t, %1; cvt.u32.u64 %0, t; }" : "=r"(a) : "l"(p));
    return a;
}
__device__ __forceinline__ void ldsm4(uint32_t* r, uint32_t addr) {
    asm volatile("ldmatrix.sync.aligned.m8n8.x4.shared.b16 {%0,%1,%2,%3}, [%4];"
                 : "=r"(r[0]), "=r"(r[1]), "=r"(r[2]), "=r"(r[3]) : "r"(addr));
}
__device__ __forceinline__ void ldsm2(uint32_t* r, uint32_t addr) {
    asm volatile("ldmatrix.sync.aligned.m8n8.x2.shared.b16 {%0,%1}, [%2];"
                 : "=r"(r[0]), "=r"(r[1]) : "r"(addr));
}
__device__ __forceinline__ void mma16(float* c, const uint32_t* a, uint32_t b0, uint32_t b1) {
    asm volatile(
        "mma.sync.aligned.m16n8k16.row.col.f32.f16.f16.f32 "
        "{%0,%1,%2,%3}, {%4,%5,%6,%7}, {%8,%9}, {%0,%1,%2,%3};"
        : "+f"(c[0]), "+f"(c[1]), "+f"(c[2]), "+f"(c[3])
        : "r"(a[0]), "r"(a[1]), "r"(a[2]), "r"(a[3]), "r"(b0), "r"(b1));
}
__device__ __forceinline__ void cp16(uint32_t dst, const void* src) {
    asm volatile("cp.async.cg.shared.global [%0], [%1], 16;" :: "r"(dst), "l"(src) : "memory");
}

// ---------------- kernel 1: build x_g_t (fp16 hi only) ----------------
__global__ __launch_bounds__(256) void prep_kernel(const float* __restrict__ x) {
    int idx = blockIdx.x * blockDim.x + threadIdx.x;
    int f4 = idx & 255;
    int bt = idx >> 8;
    if (bt >= BT) return;
    int f = f4 * 4;
    const float* xb = x + (size_t)bt * (NK * NX);
    float4 v;
    if (f < NX) {
        v = *(const float4*)(xb + f);
    } else {
        int xr = f - NX;
        float4 a1 = *(const float4*)(xb + 1 * NX + xr);
        float4 a2 = *(const float4*)(xb + 2 * NX + xr);
        float4 a3 = *(const float4*)(xb + 3 * NX + xr);
        float4 a4 = *(const float4*)(xb + 4 * NX + xr);
        v.x = (a1.x + a2.x + a3.x + a4.x) * 0.25f;
        v.y = (a1.y + a2.y + a3.y + a4.y) * 0.25f;
        v.z = (a1.z + a2.z + a3.z + a4.z) * 0.25f;
        v.w = (a1.w + a2.w + a3.w + a4.w) * 0.25f;
    }
    __half2* ph = (__half2*)&d_xa_h[(size_t)bt * NF + f];
    ph[0] = __halves2half2(__float2half_rn(v.x), __float2half_rn(v.y));
    ph[1] = __halves2half2(__float2half_rn(v.z), __float2half_rn(v.w));
}

// ---------------- kernel 1b: convert W_ih to hi/lo fp16 ----------------
__global__ __launch_bounds__(256) void wconv_kernel(const float* __restrict__ Wih) {
    int idx = (blockIdx.x * 256 + threadIdx.x) * 4;
    float4 v = *(const float4*)(Wih + idx);
    __half hx = __float2half_rn(v.x), hy = __float2half_rn(v.y);
    __half hz = __float2half_rn(v.z), hw = __float2half_rn(v.w);
    __half lx = __float2half_rn((v.x - __half2float(hx)) * LOSCALE);
    __half ly = __float2half_rn((v.y - __half2float(hy)) * LOSCALE);
    __half lz = __float2half_rn((v.z - __half2float(hz)) * LOSCALE);
    __half lw = __float2half_rn((v.w - __half2float(hw)) * LOSCALE);
    __half2* ph = (__half2*)&d_w_h[idx];
    __half2* pl = (__half2*)&d_w_l[idx];
    ph[0] = __halves2half2(hx, hy); ph[1] = __halves2half2(hz, hw);
    pl[0] = __halves2half2(lx, ly); pl[1] = __halves2half2(lz, lw);
}

// ---------------- kernel 1c: convert W_hh to hi/lo fp16 ----------------
__global__ __launch_bounds__(256) void whhconv_kernel(const float* __restrict__ Whh) {
    int idx = (blockIdx.x * 256 + threadIdx.x) * 4;   // over NG*NH
    float4 v = *(const float4*)(Whh + idx);
    __half hx = __float2half_rn(v.x), hy = __float2half_rn(v.y);
    __half hz = __float2half_rn(v.z), hw = __float2half_rn(v.w);
    __half lx = __float2half_rn((v.x - __half2float(hx)) * LOSCALE);
    __half ly = __float2half_rn((v.y - __half2float(hy)) * LOSCALE);
    __half lz = __float2half_rn((v.z - __half2float(hz)) * LOSCALE);
    __half lw = __float2half_rn((v.w - __half2float(hw)) * LOSCALE);
    __half2* ph = (__half2*)&d_whh_h[idx];
    __half2* pl = (__half2*)&d_whh_l[idx];
    ph[0] = __halves2half2(hx, hy); ph[1] = __halves2half2(hz, hw);
    pl[0] = __halves2half2(lx, ly); pl[1] = __halves2half2(lz, lw);
}

// ---------------- kernel 2: fp16x2 tensor-core GEMM, 4-stage cp.async, B-frag pipelined ----------------
__global__ __launch_bounds__(256, 1) void gemm16_kernel(const float* __restrict__ bih,
                                                        const float* __restrict__ bhh) {
    extern __shared__ __half hsm[];
    const uint32_t sbase = smem_u32(hsm);
    const int MAT   = BM * PITCH;    // 5120 halves per matrix
    const int STG_H = 3 * MAT;       // halves per stage

    const int tid = threadIdx.x;
    const int wid = tid >> 5;
    const int lid = tid & 31;
    const int g   = lid >> 2;
    const int tig = lid & 3;
    const int warpM = wid >> 1;
    const int warpN = wid & 1;
    const int ntile = blockIdx.x;
    const int mtile = blockIdx.y;

    float accH[2][8][4], accC[2][8][4];
#pragma unroll
    for (int i = 0; i < 2; i++)
#pragma unroll
        for (int j = 0; j < 8; j++)
#pragma unroll
            for (int q = 0; q < 4; q++) { accH[i][j][q] = 0.f; accC[i][j][q] = 0.f; }

    auto prefetch = [&](int i) {
        const int k0 = i * BK;
        const uint32_t sb = sbase + (uint32_t)((i & (NSTAGE - 1)) * STG_H) * 2;
#pragma unroll
        for (int j = 0; j < 6; j++) {
            int c = tid + j * 256;
            int mat = c >> 9, rem = c & 511;
            int row = rem >> 2, part = rem & 3;
            const __half* src;
            if (mat == 0)      src = d_xa_h + (size_t)(mtile * BM + row) * NF;
            else if (mat == 1) src = d_w_h + (size_t)(ntile * BN + row) * NF;
            else               src = d_w_l + (size_t)(ntile * BN + row) * NF;
            cp16(sb + (uint32_t)(mat * MAT + row * PITCH + part * 8) * 2, src + k0 + part * 8);
        }
        asm volatile("cp.async.commit_group;" ::: "memory");
    };

    prefetch(0); prefetch(1); prefetch(2);
    for (int i = 0; i < NF / BK; i++) {
        if (i <= 29)      asm volatile("cp.async.wait_group 2;" ::: "memory");
        else if (i == 30) asm volatile("cp.async.wait_group 1;" ::: "memory");
        else              asm volatile("cp.async.wait_group 0;" ::: "memory");
        __syncthreads();
        if (i < 29) prefetch(i + 3);

        const uint32_t boff = sbase + (uint32_t)((i & (NSTAGE - 1)) * STG_H) * 2;
#pragma unroll
        for (int ks = 0; ks < 2; ks++) {
            uint32_t ah[2][4];
            {
                int arow = (lid & 7) + ((lid >> 3) & 1) * 8;
                int akc = ks * 16 + (lid >> 4) * 8;
#pragma unroll
                for (int mf = 0; mf < 2; mf++) {
                    int row = warpM * 32 + mf * 16 + arow;
                    ldsm4(ah[mf], boff + (uint32_t)(row * PITCH + akc) * 2);
                }
            }
            int brow0 = (lid & 7) + ((lid >> 4) & 1) * 8;
            int bkc = ks * 16 + ((lid >> 3) & 1) * 8;
            // register double-buffer B fragments: load p+1 before p's mmas
            uint32_t bh[2][4], bl[2][4];
            {
                int row = warpN * 64 + brow0;
                uint32_t b0 = boff + (uint32_t)(MAT + row * PITCH + bkc) * 2;
                ldsm4(bh[0], b0);
                ldsm4(bl[0], b0 + (uint32_t)MAT * 2);
            }
#pragma unroll
            for (int p = 0; p < 4; p++) {
                int cur = p & 1, nxt = cur ^ 1;
                if (p < 3) {
                    int row = warpN * 64 + (p + 1) * 16 + brow0;
                    uint32_t b0 = boff + (uint32_t)(MAT + row * PITCH + bkc) * 2;
                    ldsm4(bh[nxt], b0);
                    ldsm4(bl[nxt], b0 + (uint32_t)MAT * 2);
                }
#pragma unroll
                for (int mf = 0; mf < 2; mf++) {
                    mma16(accH[mf][2 * p],     ah[mf], bh[cur][0], bh[cur][1]);
                    mma16(accC[mf][2 * p],     ah[mf], bl[cur][0], bl[cur][1]);
                    mma16(accH[mf][2 * p + 1], ah[mf], bh[cur][2], bh[cur][3]);
                    mma16(accC[mf][2 * p + 1], ah[mf], bl[cur][2], bl[cur][3]);
                }
            }
        }
    }

    // epilogue: combine, add bias, scatter to pre[t][b][g]
#pragma unroll
    for (int nf = 0; nf < 8; nf++) {
        int n = ntile * BN + warpN * 64 + nf * 8 + tig * 2;
        float bias0 = bih[n] + bhh[n];
        float bias1 = bih[n + 1] + bhh[n + 1];
#pragma unroll
        for (int mf = 0; mf < 2; mf++) {
            int m0 = mtile * BM + warpM * 32 + mf * 16 + g;
            int m1 = m0 + 8;
            {
                int b = m0 >> 8, t = m0 & 255;
                float2 v = make_float2(accH[mf][nf][0] + accC[mf][nf][0] * LOINV + bias0,
                                       accH[mf][nf][1] + accC[mf][nf][1] * LOINV + bias1);
                *(float2*)&d_pre[((size_t)t * NB + b) * NG + n] = v;
            }
            {
                int b = m1 >> 8, t = m1 & 255;
                float2 v = make_float2(accH[mf][nf][2] + accC[mf][nf][2] * LOINV + bias0,
                                       accH[mf][nf][3] + accC[mf][nf][3] * LOINV + bias1);
                *(float2*)&d_pre[((size_t)t * NB + b) * NG + n] = v;
            }
        }
    }
}

// ---------------- kernel 3: tensor-core persistent scan, split-role pipeline ----------------
// 128 CTAs (hg 0..31 x bg 0..3), 512 threads.
//   warps 0-7  (cells):   pv prefetch, matvec, gates, h store, release
//   warps 8-15 (stagers): flag wait + h staging (overlaps cells' gate phase), matvec
// matvec: z = Whh_hi@h + (Whh_lo@h)/2048  (h quantized to fp16; x2 mma)
__global__ __launch_bounds__(512) void scan_kernel() {
    extern __shared__ char smraw[];
    __half* WsH = (__half*)smraw;                 // 64 x 520
    __half* WsL = WsH + 64 * WPITCH;
    __half* HsH = WsL + 64 * WPITCH;              // 16 x 520
    float*  zb  = (float*)(HsH + 16 * WPITCH);    // 2 x 64 x 17
    unsigned* sbase_p = (unsigned*)(zb + 2 * 64 * 17);

    const int tid = threadIdx.x;
    const int cid = blockIdx.x;
    const int hg = cid & 31;
    const int bg = cid >> 5;

    if (tid == 0) {
        unsigned b;
        asm volatile("ld.acquire.gpu.global.u32 %0, [%1];" : "=r"(b) : "l"(&d_flag[cid * 32]) : "memory");
        *sbase_p = b;
    }

    // load W_hh slice hi/lo: rows r=q*16+cs -> gate G = q*512 + hg*16 + cs
    for (int i = tid; i < 4096; i += 512) {
        int r = i >> 6, k8 = (i & 63) * 8;
        int G = (r >> 4) * NH + hg * 16 + (r & 15);
        *(uint4*)&WsH[r * WPITCH + k8] = *(const uint4*)&d_whh_h[(size_t)G * NH + k8];
        *(uint4*)&WsL[r * WPITCH + k8] = *(const uint4*)&d_whh_l[(size_t)G * NH + k8];
    }
    // zero h staging (h_{-1} = 0): 16*520 halves = 1040 uint4
    for (int i = tid; i < 1040; i += 512) {
        ((uint4*)HsH)[i] = make_uint4(0u, 0u, 0u, 0u);
    }
    __syncthreads();
    const unsigned base = *sbase_p;

    // matvec warp mapping: 16 warps = 4(m) x 2(n) x 2(k-half)
    const int lid = tid & 31;
    const int wid = tid >> 5;
    const int kh = wid >> 3;
    const int w8 = wid & 7;
    const int mq = w8 & 3;
    const int nq = w8 >> 2;
    const uint32_t sb32 = smem_u32(smraw);
    const int arow = mq * 16 + (lid & 7) + ((lid >> 3) & 1) * 8;
    const uint32_t a_base = sb32 + (uint32_t)(arow * WPITCH + (lid >> 4) * 8 + kh * 256) * 2;
    const uint32_t ALO = (uint32_t)(64 * WPITCH) * 2;
    const int brow = nq * 8 + (lid & 7);
    const uint32_t b_base = sb32 + (uint32_t)(128 * WPITCH) * 2
                          + (uint32_t)(brow * WPITCH + ((lid >> 3) & 1) * 8 + kh * 256) * 2;

    // cell mapping (tid < 256)
    const int colsub = tid & 15;
    const int bsub = (tid >> 4) & 15;
    const int col = hg * 16 + colsub;
    const int bb = bg * 16 + bsub;
    float c = 0.f;

    // stager mapping (tid >= 256): col-chunk cc (8 cols), row group rg (4 rows)
    const int tp = tid & 255;
    const int cc = tp & 63;
    const int rg = tp >> 6;
    const unsigned* myflag = &d_flag[(bg * 32 + (cc >> 1)) * 32];

    for (int t = 0; t < NT; t++) {
        float pv0 = 0.f, pv1 = 0.f, pv2 = 0.f, pv3 = 0.f;
        if (tid < 256) {
            const float* pr = d_pre + ((size_t)t * NB + bb) * NG + col;
            pv0 = pr[0]; pv1 = pr[512]; pv2 = pr[1024]; pv3 = pr[1536];
        } else if (t > 0) {
            unsigned target = base + (unsigned)t;
            unsigned v;
            do {
                asm volatile("ld.acquire.gpu.global.u32 %0, [%1];" : "=r"(v) : "l"(myflag) : "memory");
            } while ((int)(v - target) < 0);
            const __half* srcH = d_hh_h[(t + 1) & 1];
#pragma unroll
            for (int j = 0; j < 4; j++) {
                int r = rg * 4 + j;
                *(uint4*)&HsH[r * WPITCH + cc * 8] = *(const uint4*)&srcH[(bg * 16 + r) * NH + cc * 8];
            }
        }
        __syncthreads();   // A: staged h visible to all matvec warps

        // matvec: 16 k-steps of k16 per warp (x2: hi + W-lo correction)
        float aH[4] = {0, 0, 0, 0}, aC[4] = {0, 0, 0, 0};
        uint32_t aaddr = a_base, baddr = b_base;
#pragma unroll
        for (int kk = 0; kk < 16; kk++) {
            uint32_t ah[4], al[4], bh[2];
            ldsm4(ah, aaddr);
            ldsm4(al, aaddr + ALO);
            ldsm2(bh, baddr);
            mma16(aH, ah, bh[0], bh[1]);
            mma16(aC, al, bh[0], bh[1]);
            aaddr += 32; baddr += 32;
        }
        {
            float* z = zb + kh * (64 * 17);
            int zr = mq * 16 + (lid >> 2);
            int zc = nq * 8 + (lid & 3) * 2;
            z[zr * 17 + zc]           = aH[0] + aC[0] * LOINV;
            z[zr * 17 + zc + 1]       = aH[1] + aC[1] * LOINV;
            z[(zr + 8) * 17 + zc]     = aH[2] + aC[2] * LOINV;
            z[(zr + 8) * 17 + zc + 1] = aH[3] + aC[3] * LOINV;
        }
        __syncthreads();   // B: zb visible to cells

        if (tid < 256) {
            float zi = zb[(0 * 16 + colsub) * 17 + bsub] + zb[64 * 17 + (0 * 16 + colsub) * 17 + bsub] + pv0;
            float zf = zb[(1 * 16 + colsub) * 17 + bsub] + zb[64 * 17 + (1 * 16 + colsub) * 17 + bsub] + pv1;
            float zg = zb[(2 * 16 + colsub) * 17 + bsub] + zb[64 * 17 + (2 * 16 + colsub) * 17 + bsub] + pv2;
            float zo = zb[(3 * 16 + colsub) * 17 + bsub] + zb[64 * 17 + (3 * 16 + colsub) * 17 + bsub] + pv3;
            float ig = 1.f / (1.f + expf(-zi));
            float fg = 1.f / (1.f + expf(-zf));
            float gg = tanhf(zg);
            float og = 1.f / (1.f + expf(-zo));
            c = fg * c + ig * gg;
            float hv = og * tanhf(c);
            d_hh_h[t & 1][bb * NH + col] = __float2half_rn(hv);
            asm volatile("bar.sync 1, 256;" ::: "memory");   // cells only
            if (tid == 0) {
                asm volatile("st.release.gpu.global.u32 [%0], %1;"
                             :: "l"(&d_flag[cid * 32]), "r"(base + (unsigned)t + 1u) : "memory");
            }
            d_houts[(size_t)t * (NB * NH) + bb * NH + col] = hv;
        }
        // stagers skip straight to next step's flag wait (overlaps cells' gate phase)
    }
}

// ---------------- kernel 4: per-t BN stats -> scale/shift ----------------
__global__ __launch_bounds__(256) void stats_kernel(const float* __restrict__ gamma,
                                                    const float* __restrict__ beta) {
    int t = blockIdx.x;
    const float4* p = (const float4*)(d_houts + (size_t)t * (NB * NH));
    float s = 0.f, ss = 0.f;
    for (int i = threadIdx.x; i < (NB * NH) / 4; i += 256) {
        float4 v = p[i];
        s  += v.x + v.y + v.z + v.w;
        ss += v.x * v.x + v.y * v.y + v.z * v.z + v.w * v.w;
    }
#pragma unroll
    for (int o = 16; o > 0; o >>= 1) {
        s  += __shfl_down_sync(0xffffffffu, s, o);
        ss += __shfl_down_sync(0xffffffffu, ss, o);
    }
    __shared__ float rs[8], rss[8];
    int w = threadIdx.x >> 5;
    if ((threadIdx.x & 31) == 0) { rs[w] = s; rss[w] = ss; }
    __syncthreads();
    if (threadIdx.x == 0) {
        float S = 0.f, SS = 0.f;
#pragma unroll
        for (int i = 0; i < 8; i++) { S += rs[i]; SS += rss[i]; }
        float mean = S * (1.f / (NB * NH));
        float var = SS * (1.f / (NB * NH)) - mean * mean;
        float sc = gamma[t] * rsqrtf(var + 1e-5f);
        d_scaleArr[t] = sc;
        d_shiftArr[t] = beta[t] - mean * sc;
    }
}

// ---------------- kernel 5: elu(BN(h)) mean over t -> out[b][h] ----------------
__global__ __launch_bounds__(256) void final_kernel(float* __restrict__ out) {
    int idx = blockIdx.x * 256 + threadIdx.x;
    float acc = 0.f;
#pragma unroll 4
    for (int t = 0; t < NT; t++) {
        float v = d_houts[(size_t)t * (NB * NH) + idx];
        float u = v * d_scaleArr[t] + d_shiftArr[t];
        acc += (u > 0.f) ? u : expm1f(u);
    }
    out[idx] = acc * (1.f / NT);
}

// ---------------- launch ----------------
extern "C" void kernel_launch(void* const* d_in, const int* in_sizes, int n_in,
                              void* d_out, int out_size) {
    const float* x     = (const float*)d_in[0];
    const float* Wih   = (const float*)d_in[1];
    const float* Whh   = (const float*)d_in[2];
    const float* bih   = (const float*)d_in[3];
    const float* bhh   = (const float*)d_in[4];
    const float* gamma = (const float*)d_in[5];
    const float* beta  = (const float*)d_in[6];
    float* out = (float*)d_out;

    prep_kernel<<<BT, 256>>>(x);
    wconv_kernel<<<(NG * NF / 4) / 256, 256>>>(Wih);
    whhconv_kernel<<<(NG * NH / 4) / 256, 256>>>(Whh);

    int gsmem = NSTAGE * 3 * BM * PITCH * 2;   // 122,880 B
    cudaFuncSetAttribute(gemm16_kernel, cudaFuncAttributeMaxDynamicSharedMemorySize, gsmem);
    dim3 ggrid(NG / BN, BT / BM);              // (16, 128)
    gemm16_kernel<<<ggrid, 256, gsmem>>>(bih, bhh);

    int ssmem = (64 * WPITCH + 64 * WPITCH + 16 * WPITCH) * 2
              + 2 * 64 * 17 * 4 + 16;          // 158,480 B
    cudaFuncSetAttribute(scan_kernel, cudaFuncAttributeMaxDynamicSharedMemorySize, ssmem);
    scan_kernel<<<128, 512, ssmem>>>();

    stats_kernel<<<NT, 256>>>(gamma, beta);
    final_kernel<<<(NB * NH) / 256, 256>>>(out);
}

// round 11
// speedup vs baseline: 5.0109x; 1.3000x over previous
#include <cuda_runtime.h>
#include <cuda_fp16.h>
#include <cstdint>
#include <math.h>

// Problem constants
#define NB   64     // batch
#define NT   256    // time
#define NK   5
#define NX   512
#define NH   512
#define NG   2048   // 4*H
#define NF   1024   // 2*X
#define BT   16384  // NB*NT

// fp16 GEMM tile config
#define BM   128
#define BN   128
#define BK   32
#define PITCH 40            // smem row pitch in halves (80B) -> ldmatrix conflict-free
#define NSTAGE 4

// scan smem layout (in halves): WsH 64x520, HsH 16x520, then zbuf
#define WPITCH 520

// ---------------- device scratch (static: no allocations allowed) ----------------
__device__ __half d_xa_h[(size_t)BT * NF];         // x_g_t, fp16
__device__ __half d_w_h[(size_t)NG * NF];          // W_ih fp16
__device__ __half d_whh_h[(size_t)NG * NH];        // W_hh fp16
__device__ __half d_hh_h[2][NB * NH];              // h ping-pong (fp16)
__device__ float d_pre[(size_t)NT * NB * NG];      // pre-gates, [t][b][g]
__device__ float d_houts[(size_t)NT * NB * NH];    // all h_t (fp32, for BN)
__device__ float d_scaleArr[NT];
__device__ float d_shiftArr[NT];
__device__ unsigned d_flag[128 * 32];              // per-CTA generation flags, 128B apart

// ---------------- mma / ldmatrix helpers ----------------
__device__ __forceinline__ uint32_t smem_u32(const void* p) {
    uint32_t a;
    asm("{ .reg .u64 t; cvta.to.shared.u64 t, %1; cvt.u32.u64 %0, t; }" : "=r"(a) : "l"(p));
    return a;
}
__device__ __forceinline__ void ldsm4(uint32_t* r, uint32_t addr) {
    asm volatile("ldmatrix.sync.aligned.m8n8.x4.shared.b16 {%0,%1,%2,%3}, [%4];"
                 : "=r"(r[0]), "=r"(r[1]), "=r"(r[2]), "=r"(r[3]) : "r"(addr));
}
__device__ __forceinline__ void ldsm2(uint32_t* r, uint32_t addr) {
    asm volatile("ldmatrix.sync.aligned.m8n8.x2.shared.b16 {%0,%1}, [%2];"
                 : "=r"(r[0]), "=r"(r[1]) : "r"(addr));
}
__device__ __forceinline__ void mma16(float* c, const uint32_t* a, uint32_t b0, uint32_t b1) {
    asm volatile(
        "mma.sync.aligned.m16n8k16.row.col.f32.f16.f16.f32 "
        "{%0,%1,%2,%3}, {%4,%5,%6,%7}, {%8,%9}, {%0,%1,%2,%3};"
        : "+f"(c[0]), "+f"(c[1]), "+f"(c[2]), "+f"(c[3])
        : "r"(a[0]), "r"(a[1]), "r"(a[2]), "r"(a[3]), "r"(b0), "r"(b1));
}
__device__ __forceinline__ void cp16(uint32_t dst, const void* src) {
    asm volatile("cp.async.cg.shared.global [%0], [%1], 16;" :: "r"(dst), "l"(src) : "memory");
}

// ---------------- kernel 1: build x_g_t (fp16) ----------------
__global__ __launch_bounds__(256) void prep_kernel(const float* __restrict__ x) {
    int idx = blockIdx.x * blockDim.x + threadIdx.x;
    int f4 = idx & 255;
    int bt = idx >> 8;
    if (bt >= BT) return;
    int f = f4 * 4;
    const float* xb = x + (size_t)bt * (NK * NX);
    float4 v;
    if (f < NX) {
        v = *(const float4*)(xb + f);
    } else {
        int xr = f - NX;
        float4 a1 = *(const float4*)(xb + 1 * NX + xr);
        float4 a2 = *(const float4*)(xb + 2 * NX + xr);
        float4 a3 = *(const float4*)(xb + 3 * NX + xr);
        float4 a4 = *(const float4*)(xb + 4 * NX + xr);
        v.x = (a1.x + a2.x + a3.x + a4.x) * 0.25f;
        v.y = (a1.y + a2.y + a3.y + a4.y) * 0.25f;
        v.z = (a1.z + a2.z + a3.z + a4.z) * 0.25f;
        v.w = (a1.w + a2.w + a3.w + a4.w) * 0.25f;
    }
    __half2* ph = (__half2*)&d_xa_h[(size_t)bt * NF + f];
    ph[0] = __halves2half2(__float2half_rn(v.x), __float2half_rn(v.y));
    ph[1] = __halves2half2(__float2half_rn(v.z), __float2half_rn(v.w));
}

// ---------------- kernel 1b: convert W_ih to fp16 ----------------
__global__ __launch_bounds__(256) void wconv_kernel(const float* __restrict__ Wih) {
    int idx = (blockIdx.x * 256 + threadIdx.x) * 4;
    float4 v = *(const float4*)(Wih + idx);
    __half2* ph = (__half2*)&d_w_h[idx];
    ph[0] = __halves2half2(__float2half_rn(v.x), __float2half_rn(v.y));
    ph[1] = __halves2half2(__float2half_rn(v.z), __float2half_rn(v.w));
}

// ---------------- kernel 1c: convert W_hh to fp16 ----------------
__global__ __launch_bounds__(256) void whhconv_kernel(const float* __restrict__ Whh) {
    int idx = (blockIdx.x * 256 + threadIdx.x) * 4;   // over NG*NH
    float4 v = *(const float4*)(Whh + idx);
    __half2* ph = (__half2*)&d_whh_h[idx];
    ph[0] = __halves2half2(__float2half_rn(v.x), __float2half_rn(v.y));
    ph[1] = __halves2half2(__float2half_rn(v.z), __float2half_rn(v.w));
}

// ---------------- kernel 2: fp16 tensor-core GEMM, 4-stage cp.async, 2 CTAs/SM ----------------
// pre = xg @ Wih^T + bias.  M=16384, N=2048, K=1024.
__global__ __launch_bounds__(256, 2) void gemm16_kernel(const float* __restrict__ bih,
                                                        const float* __restrict__ bhh) {
    extern __shared__ __half hsm[];
    const uint32_t sbase = smem_u32(hsm);
    const int MAT   = BM * PITCH;    // 5120 halves per matrix
    const int STG_H = 2 * MAT;       // halves per stage (A, B)

    const int tid = threadIdx.x;
    const int wid = tid >> 5;
    const int lid = tid & 31;
    const int g   = lid >> 2;
    const int tig = lid & 3;
    const int warpM = wid >> 1;
    const int warpN = wid & 1;
    const int ntile = blockIdx.x;
    const int mtile = blockIdx.y;

    float accH[2][8][4];
#pragma unroll
    for (int i = 0; i < 2; i++)
#pragma unroll
        for (int j = 0; j < 8; j++)
#pragma unroll
            for (int q = 0; q < 4; q++) accH[i][j][q] = 0.f;

    // 1024 16B-segments per stage, 4 per thread: mat = c>>9 (0:A 1:B)
    auto prefetch = [&](int i) {
        const int k0 = i * BK;
        const uint32_t sb = sbase + (uint32_t)((i & (NSTAGE - 1)) * STG_H) * 2;
#pragma unroll
        for (int j = 0; j < 4; j++) {
            int c = tid + j * 256;
            int mat = c >> 9, rem = c & 511;
            int row = rem >> 2, part = rem & 3;
            const __half* src = (mat == 0) ? d_xa_h + (size_t)(mtile * BM + row) * NF
                                           : d_w_h + (size_t)(ntile * BN + row) * NF;
            cp16(sb + (uint32_t)(mat * MAT + row * PITCH + part * 8) * 2, src + k0 + part * 8);
        }
        asm volatile("cp.async.commit_group;" ::: "memory");
    };

    prefetch(0); prefetch(1); prefetch(2);
    for (int i = 0; i < NF / BK; i++) {
        if (i <= 29)      asm volatile("cp.async.wait_group 2;" ::: "memory");
        else if (i == 30) asm volatile("cp.async.wait_group 1;" ::: "memory");
        else              asm volatile("cp.async.wait_group 0;" ::: "memory");
        __syncthreads();
        if (i < 29) prefetch(i + 3);

        const uint32_t boff = sbase + (uint32_t)((i & (NSTAGE - 1)) * STG_H) * 2;
#pragma unroll
        for (int ks = 0; ks < 2; ks++) {
            uint32_t ah[2][4];
            {
                int arow = (lid & 7) + ((lid >> 3) & 1) * 8;
                int akc = ks * 16 + (lid >> 4) * 8;
#pragma unroll
                for (int mf = 0; mf < 2; mf++) {
                    int row = warpM * 32 + mf * 16 + arow;
                    ldsm4(ah[mf], boff + (uint32_t)(row * PITCH + akc) * 2);
                }
            }
            int brow0 = (lid & 7) + ((lid >> 4) & 1) * 8;
            int bkc = ks * 16 + ((lid >> 3) & 1) * 8;
            uint32_t bh[2][4];
            {
                int row = warpN * 64 + brow0;
                ldsm4(bh[0], boff + (uint32_t)(MAT + row * PITCH + bkc) * 2);
            }
#pragma unroll
            for (int p = 0; p < 4; p++) {
                int cur = p & 1, nxt = cur ^ 1;
                if (p < 3) {
                    int row = warpN * 64 + (p + 1) * 16 + brow0;
                    ldsm4(bh[nxt], boff + (uint32_t)(MAT + row * PITCH + bkc) * 2);
                }
#pragma unroll
                for (int mf = 0; mf < 2; mf++) {
                    mma16(accH[mf][2 * p],     ah[mf], bh[cur][0], bh[cur][1]);
                    mma16(accH[mf][2 * p + 1], ah[mf], bh[cur][2], bh[cur][3]);
                }
            }
        }
    }

    // epilogue: add bias, scatter to pre[t][b][g]
#pragma unroll
    for (int nf = 0; nf < 8; nf++) {
        int n = ntile * BN + warpN * 64 + nf * 8 + tig * 2;
        float bias0 = bih[n] + bhh[n];
        float bias1 = bih[n + 1] + bhh[n + 1];
#pragma unroll
        for (int mf = 0; mf < 2; mf++) {
            int m0 = mtile * BM + warpM * 32 + mf * 16 + g;
            int m1 = m0 + 8;
            {
                int b = m0 >> 8, t = m0 & 255;
                float2 v = make_float2(accH[mf][nf][0] + bias0, accH[mf][nf][1] + bias1);
                *(float2*)&d_pre[((size_t)t * NB + b) * NG + n] = v;
            }
            {
                int b = m1 >> 8, t = m1 & 255;
                float2 v = make_float2(accH[mf][nf][2] + bias0, accH[mf][nf][3] + bias1);
                *(float2*)&d_pre[((size_t)t * NB + b) * NG + n] = v;
            }
        }
    }
}

// ---------------- kernel 3: tensor-core persistent scan, split-role pipeline ----------------
// 128 CTAs (hg 0..31 x bg 0..3), 512 threads.
//   warps 0-7  (cells):   pv prefetch, matvec, gates, h store, release
//   warps 8-15 (stagers): flag wait + h staging (overlaps cells' gate phase), matvec
// matvec: z = Whh @ h  (pure fp16 operands, fp32 accum)
__global__ __launch_bounds__(512) void scan_kernel() {
    extern __shared__ char smraw[];
    __half* WsH = (__half*)smraw;                 // 64 x 520
    __half* HsH = WsH + 64 * WPITCH;              // 16 x 520
    float*  zb  = (float*)(HsH + 16 * WPITCH);    // 2 x 64 x 17
    unsigned* sbase_p = (unsigned*)(zb + 2 * 64 * 17);

    const int tid = threadIdx.x;
    const int cid = blockIdx.x;
    const int hg = cid & 31;
    const int bg = cid >> 5;

    if (tid == 0) {
        unsigned b;
        asm volatile("ld.acquire.gpu.global.u32 %0, [%1];" : "=r"(b) : "l"(&d_flag[cid * 32]) : "memory");
        *sbase_p = b;
    }

    // load W_hh slice: rows r=q*16+cs -> gate G = q*512 + hg*16 + cs
    for (int i = tid; i < 4096; i += 512) {
        int r = i >> 6, k8 = (i & 63) * 8;
        int G = (r >> 4) * NH + hg * 16 + (r & 15);
        *(uint4*)&WsH[r * WPITCH + k8] = *(const uint4*)&d_whh_h[(size_t)G * NH + k8];
    }
    // zero h staging (h_{-1} = 0): 16*520 halves = 1040 uint4
    for (int i = tid; i < 1040; i += 512) {
        ((uint4*)HsH)[i] = make_uint4(0u, 0u, 0u, 0u);
    }
    __syncthreads();
    const unsigned base = *sbase_p;

    // matvec warp mapping: 16 warps = 4(m) x 2(n) x 2(k-half)
    const int lid = tid & 31;
    const int wid = tid >> 5;
    const int kh = wid >> 3;
    const int w8 = wid & 7;
    const int mq = w8 & 3;
    const int nq = w8 >> 2;
    const uint32_t sb32 = smem_u32(smraw);
    const int arow = mq * 16 + (lid & 7) + ((lid >> 3) & 1) * 8;
    const uint32_t a_base = sb32 + (uint32_t)(arow * WPITCH + (lid >> 4) * 8 + kh * 256) * 2;
    const int brow = nq * 8 + (lid & 7);
    const uint32_t b_base = sb32 + (uint32_t)(64 * WPITCH) * 2
                          + (uint32_t)(brow * WPITCH + ((lid >> 3) & 1) * 8 + kh * 256) * 2;

    // cell mapping (tid < 256)
    const int colsub = tid & 15;
    const int bsub = (tid >> 4) & 15;
    const int col = hg * 16 + colsub;
    const int bb = bg * 16 + bsub;
    float c = 0.f;

    // stager mapping (tid >= 256): col-chunk cc (8 cols), row group rg (4 rows)
    const int tp = tid & 255;
    const int cc = tp & 63;
    const int rg = tp >> 6;
    const unsigned* myflag = &d_flag[(bg * 32 + (cc >> 1)) * 32];

    for (int t = 0; t < NT; t++) {
        float pv0 = 0.f, pv1 = 0.f, pv2 = 0.f, pv3 = 0.f;
        if (tid < 256) {
            const float* pr = d_pre + ((size_t)t * NB + bb) * NG + col;
            pv0 = pr[0]; pv1 = pr[512]; pv2 = pr[1024]; pv3 = pr[1536];
        } else if (t > 0) {
            unsigned target = base + (unsigned)t;
            unsigned v;
            do {
                asm volatile("ld.acquire.gpu.global.u32 %0, [%1];" : "=r"(v) : "l"(myflag) : "memory");
            } while ((int)(v - target) < 0);
            const __half* srcH = d_hh_h[(t + 1) & 1];
#pragma unroll
            for (int j = 0; j < 4; j++) {
                int r = rg * 4 + j;
                *(uint4*)&HsH[r * WPITCH + cc * 8] = *(const uint4*)&srcH[(bg * 16 + r) * NH + cc * 8];
            }
        }
        __syncthreads();   // staged h visible to all matvec warps

        // matvec: 16 k-steps of k16 per warp
        float aH[4] = {0, 0, 0, 0};
        uint32_t aaddr = a_base, baddr = b_base;
#pragma unroll
        for (int kk = 0; kk < 16; kk++) {
            uint32_t ah[4], bh[2];
            ldsm4(ah, aaddr);
            ldsm2(bh, baddr);
            mma16(aH, ah, bh[0], bh[1]);
            aaddr += 32; baddr += 32;
        }
        {
            float* z = zb + kh * (64 * 17);
            int zr = mq * 16 + (lid >> 2);
            int zc = nq * 8 + (lid & 3) * 2;
            z[zr * 17 + zc]           = aH[0];
            z[zr * 17 + zc + 1]       = aH[1];
            z[(zr + 8) * 17 + zc]     = aH[2];
            z[(zr + 8) * 17 + zc + 1] = aH[3];
        }
        __syncthreads();   // zb visible to cells

        if (tid < 256) {
            float zi = zb[(0 * 16 + colsub) * 17 + bsub] + zb[64 * 17 + (0 * 16 + colsub) * 17 + bsub] + pv0;
            float zf = zb[(1 * 16 + colsub) * 17 + bsub] + zb[64 * 17 + (1 * 16 + colsub) * 17 + bsub] + pv1;
            float zg = zb[(2 * 16 + colsub) * 17 + bsub] + zb[64 * 17 + (2 * 16 + colsub) * 17 + bsub] + pv2;
            float zo = zb[(3 * 16 + colsub) * 17 + bsub] + zb[64 * 17 + (3 * 16 + colsub) * 17 + bsub] + pv3;
            float ig = 1.f / (1.f + expf(-zi));
            float fg = 1.f / (1.f + expf(-zf));
            float gg = tanhf(zg);
            float og = 1.f / (1.f + expf(-zo));
            c = fg * c + ig * gg;
            float hv = og * tanhf(c);
            d_hh_h[t & 1][bb * NH + col] = __float2half_rn(hv);
            asm volatile("bar.sync 1, 256;" ::: "memory");   // cells only
            if (tid == 0) {
                asm volatile("st.release.gpu.global.u32 [%0], %1;"
                             :: "l"(&d_flag[cid * 32]), "r"(base + (unsigned)t + 1u) : "memory");
            }
            d_houts[(size_t)t * (NB * NH) + bb * NH + col] = hv;
        }
        // stagers skip straight to next step's flag wait (overlaps cells' gate phase)
    }
}

// ---------------- kernel 4: per-t BN stats -> scale/shift ----------------
__global__ __launch_bounds__(256) void stats_kernel(const float* __restrict__ gamma,
                                                    const float* __restrict__ beta) {
    int t = blockIdx.x;
    const float4* p = (const float4*)(d_houts + (size_t)t * (NB * NH));
    float s = 0.f, ss = 0.f;
    for (int i = threadIdx.x; i < (NB * NH) / 4; i += 256) {
        float4 v = p[i];
        s  += v.x + v.y + v.z + v.w;
        ss += v.x * v.x + v.y * v.y + v.z * v.z + v.w * v.w;
    }
#pragma unroll
    for (int o = 16; o > 0; o >>= 1) {
        s  += __shfl_down_sync(0xffffffffu, s, o);
        ss += __shfl_down_sync(0xffffffffu, ss, o);
    }
    __shared__ float rs[8], rss[8];
    int w = threadIdx.x >> 5;
    if ((threadIdx.x & 31) == 0) { rs[w] = s; rss[w] = ss; }
    __syncthreads();
    if (threadIdx.x == 0) {
        float S = 0.f, SS = 0.f;
#pragma unroll
        for (int i = 0; i < 8; i++) { S += rs[i]; SS += rss[i]; }
        float mean = S * (1.f / (NB * NH));
        float var = SS * (1.f / (NB * NH)) - mean * mean;
        float sc = gamma[t] * rsqrtf(var + 1e-5f);
        d_scaleArr[t] = sc;
        d_shiftArr[t] = beta[t] - mean * sc;
    }
}

// ---------------- kernel 5: elu(BN(h)) mean over t -> out[b][h] ----------------
__global__ __launch_bounds__(256) void final_kernel(float* __restrict__ out) {
    int idx = blockIdx.x * 256 + threadIdx.x;
    float acc = 0.f;
#pragma unroll 4
    for (int t = 0; t < NT; t++) {
        float v = d_houts[(size_t)t * (NB * NH) + idx];
        float u = v * d_scaleArr[t] + d_shiftArr[t];
        acc += (u > 0.f) ? u : expm1f(u);
    }
    out[idx] = acc * (1.f / NT);
}

// ---------------- launch ----------------
extern "C" void kernel_launch(void* const* d_in, const int* in_sizes, int n_in,
                              void* d_out, int out_size) {
    const float* x     = (const float*)d_in[0];
    const float* Wih   = (const float*)d_in[1];
    const float* Whh   = (const float*)d_in[2];
    const float* bih   = (const float*)d_in[3];
    const float* bhh   = (const float*)d_in[4];
    const float* gamma = (const float*)d_in[5];
    const float* beta  = (const float*)d_in[6];
    float* out = (float*)d_out;

    prep_kernel<<<BT, 256>>>(x);
    wconv_kernel<<<(NG * NF / 4) / 256, 256>>>(Wih);
    whhconv_kernel<<<(NG * NH / 4) / 256, 256>>>(Whh);

    int gsmem = NSTAGE * 2 * BM * PITCH * 2;   // 81,920 B (4-stage, 2 matrices) -> 2 CTAs/SM
    cudaFuncSetAttribute(gemm16_kernel, cudaFuncAttributeMaxDynamicSharedMemorySize, gsmem);
    dim3 ggrid(NG / BN, BT / BM);              // (16, 128)
    gemm16_kernel<<<ggrid, 256, gsmem>>>(bih, bhh);

    int ssmem = (64 * WPITCH + 16 * WPITCH) * 2
              + 2 * 64 * 17 * 4 + 16;          // 91,920 B
    cudaFuncSetAttribute(scan_kernel, cudaFuncAttributeMaxDynamicSharedMemorySize, ssmem);
    scan_kernel<<<128, 512, ssmem>>>();

    stats_kernel<<<NT, 256>>>(gamma, beta);
    final_kernel<<<(NB * NH) / 256, 256>>>(out);
}